// round 14
// baseline (speedup 1.0000x reference)
#include <cuda_runtime.h>
#include <cuda_fp16.h>
#include <math.h>
#include <stdint.h>

#define NN 50000
#define NE 800000
#define FI 128
#define FH 256
#define K1 25000
#define K2 12500
#define NSCAN 49  // ceil(NN/1024)

// ---------------- scratch (device globals; zero-init, allocation-free) -----
__device__ __align__(16) __half g_xah[NN * FH];  // L4 gather input / L5 gemm out (half)
__device__ __align__(16) float g_h[NN * FH];     // L0 gemm out
__device__ __align__(16) float g_hid0[NN * FH];  // L1 out (full)
__device__ __align__(16) float g_hid1[NN * FH];  // L2 out (scattered; else 0)
__device__ __align__(16) float g_h4[NN * FH];    // L4 out (scattered; else 0)
__device__ __align__(16) __half g_xh[NN * FH];   // gemm A hi
__device__ __align__(16) __half g_xl[NN * FH];   // gemm A lo
__device__ __align__(16) __half g_wth[327680];   // weights hi (transposed)
__device__ __align__(16) __half g_wtl[327680];   // weights lo
__device__ float g_zpart[NN * 2];                // fused score partials
__device__ int g_degout[NN];
__device__ int g_degO1[NN], g_degI1[NN], g_degO2[NN], g_degI2[NN];
__device__ float g_comb1[NN], g_dov1[NN], g_div1[NN];
__device__ float g_comb2[NN], g_dov2[NN], g_div2[NN];
__device__ float g_scores[NN];
__device__ unsigned g_keys[NN];
__device__ int g_rowstart[NN + 1];
__device__ int g_rowoff[NN];
__device__ int g_csrsrc[NE];
__device__ int g_alist1[NN], g_alist2[NN];
__device__ int g_nact[2];
__device__ unsigned g_prefix;
__device__ int g_bsum[64];

#define WO_EMB  0
#define WO_ENC0 32768
#define WO_ENC1 98304
#define WO_BOT  163840
#define WO_DEC0 229376
#define WO_DEC1 294912

__device__ __forceinline__ unsigned f2k(float f) {
    unsigned u = __float_as_uint(f);
    return (u & 0x80000000u) ? ~u : (u | 0x80000000u);
}
__device__ __forceinline__ void split4(float4 v, __half2* ph, __half2* pl) {
    __half h0 = __float2half_rn(v.x), h1 = __float2half_rn(v.y);
    __half h2 = __float2half_rn(v.z), h3 = __float2half_rn(v.w);
    __half l0 = __float2half_rn(v.x - __half2float(h0));
    __half l1 = __float2half_rn(v.y - __half2float(h1));
    __half l2 = __float2half_rn(v.z - __half2float(h2));
    __half l3 = __float2half_rn(v.w - __half2float(h3));
    ph[0] = __halves2half2(h0, h1); ph[1] = __halves2half2(h2, h3);
    pl[0] = __halves2half2(l0, l1); pl[1] = __halves2half2(l2, l3);
}

// ---------------- prep ----------------
__global__ void prep_kernel(const float* __restrict__ We, const float* __restrict__ W0,
                            const float* __restrict__ W1, const float* __restrict__ Wb,
                            const float* __restrict__ Wd0, const float* __restrict__ Wd1) {
    int i = blockIdx.x * blockDim.x + threadIdx.x;
    if (i < NN) {
        g_rowoff[i] = 0; g_degout[i] = 0;
        g_degO1[i] = 0; g_degI1[i] = 0;
        g_degO2[i] = 0; g_degI2[i] = 0;
    }
    if (i == 0) { g_nact[0] = 0; g_nact[1] = 0; g_rowstart[NN] = NE; }
    float w; int o;
    if (i < 32768) {
        int k = i >> 8, n = i & 255;
        w = We[i]; o = WO_EMB + n * 128 + k;
    } else if (i < 98304) {
        int j = i - 32768; int k = j >> 8, n = j & 255;
        w = W0[j]; o = WO_ENC0 + n * 256 + k;
    } else if (i < 163840) {
        int j = i - 98304; int k = j >> 8, n = j & 255;
        w = W1[j]; o = WO_ENC1 + n * 256 + k;
    } else if (i < 229376) {
        int j = i - 163840; int k = j >> 8, n = j & 255;
        w = Wb[j]; o = WO_BOT + n * 256 + k;
    } else if (i < 294912) {
        int j = i - 229376; int k = j >> 8, n = j & 255;
        w = Wd0[j]; o = WO_DEC0 + n * 256 + k;
    } else if (i < 327680) {
        int j = i - 294912; int k = j >> 7, n = j & 127;
        w = Wd1[j]; o = WO_DEC1 + n * 256 + k;
    } else return;
    __half h = __float2half_rn(w);
    g_wth[o] = h;
    g_wtl[o] = __float2half_rn(w - __half2float(h));
}

// ---------------- CSR build ----------------
__global__ void hist_kernel(const int* __restrict__ src, const int* __restrict__ dst) {
    int e = blockIdx.x * blockDim.x + threadIdx.x;
    if (e < NE) {
        atomicAdd(&g_rowoff[dst[e]], 1);
        atomicAdd(&g_degout[src[e]], 1);
    }
}
__global__ void scan1_kernel() {
    int b = blockIdx.x, t = threadIdx.x;
    int i = b * 1024 + t;
    int v = (i < NN) ? g_rowoff[i] : 0;
    int lane = t & 31, wid = t >> 5;
    int x = v;
#pragma unroll
    for (int off = 1; off < 32; off <<= 1) {
        int y = __shfl_up_sync(0xFFFFFFFFu, x, off);
        if (lane >= off) x += y;
    }
    __shared__ int ws[32];
    if (lane == 31) ws[wid] = x;
    __syncthreads();
    if (wid == 0) {
        int y = ws[lane];
#pragma unroll
        for (int off = 1; off < 32; off <<= 1) {
            int z = __shfl_up_sync(0xFFFFFFFFu, y, off);
            if (lane >= off) y += z;
        }
        ws[lane] = y;
    }
    __syncthreads();
    int base = wid ? ws[wid - 1] : 0;
    if (i < NN) g_rowstart[i] = base + x - v;
    if (t == 1023) g_bsum[b] = base + x;
}
__global__ void scan3_kernel() {
    __shared__ int boff[NSCAN + 1];
    int t = threadIdx.x;
    if (t < NSCAN) boff[t + 1] = g_bsum[t];
    __syncthreads();
    if (t == 0) {
        boff[0] = 0;
        for (int b = 1; b <= NSCAN; b++) boff[b] += boff[b - 1];
    }
    __syncthreads();
    int i = blockIdx.x * blockDim.x + t;
    if (i < NN) {
        int rs = g_rowstart[i] + boff[i >> 10];
        g_rowstart[i] = rs;
        g_rowoff[i] = rs;
    }
}
__global__ void scatter_kernel(const int* __restrict__ src, const int* __restrict__ dst) {
    int e = blockIdx.x * blockDim.x + threadIdx.x;
    if (e < NE) {
        int pos = atomicAdd(&g_rowoff[dst[e]], 1);
        g_csrsrc[pos] = src[e];
    }
}

// ---------------- CSR aggregation: 1 warp per node (fp32 input) ----------------
// BR=1: skip zero scales (masked layers). BR=0: branch-free 2-wide unroll.
template <int BR>
__global__ void agg_half_kernel(const float* __restrict__ x,
                                const float* __restrict__ smul, const int* __restrict__ degsrc,
                                const float* __restrict__ divv, const int* __restrict__ alist,
                                __half* __restrict__ oh, __half* __restrict__ ol,
                                int F, int nnodes) {
    int wid = (blockIdx.x * blockDim.x + threadIdx.x) >> 5;
    if (wid >= nnodes) return;
    int lane = threadIdx.x & 31;
    int node = alist ? alist[wid] : wid;
    int s = g_rowstart[node], e = g_rowstart[node + 1];
    int f4 = F >> 2;
    bool wide = (f4 == 64);
    float4 a0 = make_float4(0.f, 0.f, 0.f, 0.f);
    float4 a1 = make_float4(0.f, 0.f, 0.f, 0.f);
    for (int b = s; b < e; b += 32) {
        int nn = min(32, e - b);
        int si = 0; float sc = 0.f;
        if (lane < nn) {
            si = g_csrsrc[b + lane];
            if (smul) sc = smul[si];
            else if (degsrc) sc = rsqrtf((float)max(degsrc[si], 1));
            else sc = 1.f;
        }
        if (BR) {
            for (int k = 0; k < nn; k++) {
                int sik = __shfl_sync(0xFFFFFFFFu, si, k);
                float sck = __shfl_sync(0xFFFFFFFFu, sc, k);
                if (sck != 0.f) {
                    const float4* xp = (const float4*)x + (size_t)sik * f4 + lane;
                    float4 v = xp[0];
                    a0.x = fmaf(v.x, sck, a0.x); a0.y = fmaf(v.y, sck, a0.y);
                    a0.z = fmaf(v.z, sck, a0.z); a0.w = fmaf(v.w, sck, a0.w);
                    if (wide) {
                        float4 v1 = xp[32];
                        a1.x = fmaf(v1.x, sck, a1.x); a1.y = fmaf(v1.y, sck, a1.y);
                        a1.z = fmaf(v1.z, sck, a1.z); a1.w = fmaf(v1.w, sck, a1.w);
                    }
                }
            }
        } else {
            int k = 0;
            for (; k + 2 <= nn; k += 2) {
                int s0 = __shfl_sync(0xFFFFFFFFu, si, k);
                int s1 = __shfl_sync(0xFFFFFFFFu, si, k + 1);
                float c0 = __shfl_sync(0xFFFFFFFFu, sc, k);
                float c1 = __shfl_sync(0xFFFFFFFFu, sc, k + 1);
                const float4* x0 = (const float4*)x + (size_t)s0 * f4 + lane;
                const float4* x1 = (const float4*)x + (size_t)s1 * f4 + lane;
                float4 v0 = x0[0];
                float4 v1 = x1[0];
                a0.x = fmaf(v0.x, c0, a0.x); a0.y = fmaf(v0.y, c0, a0.y);
                a0.z = fmaf(v0.z, c0, a0.z); a0.w = fmaf(v0.w, c0, a0.w);
                a0.x = fmaf(v1.x, c1, a0.x); a0.y = fmaf(v1.y, c1, a0.y);
                a0.z = fmaf(v1.z, c1, a0.z); a0.w = fmaf(v1.w, c1, a0.w);
                if (wide) {
                    float4 w0 = x0[32];
                    float4 w1 = x1[32];
                    a1.x = fmaf(w0.x, c0, a1.x); a1.y = fmaf(w0.y, c0, a1.y);
                    a1.z = fmaf(w0.z, c0, a1.z); a1.w = fmaf(w0.w, c0, a1.w);
                    a1.x = fmaf(w1.x, c1, a1.x); a1.y = fmaf(w1.y, c1, a1.y);
                    a1.z = fmaf(w1.z, c1, a1.z); a1.w = fmaf(w1.w, c1, a1.w);
                }
            }
            if (k < nn) {
                int s0 = __shfl_sync(0xFFFFFFFFu, si, k);
                float c0 = __shfl_sync(0xFFFFFFFFu, sc, k);
                const float4* x0 = (const float4*)x + (size_t)s0 * f4 + lane;
                float4 v0 = x0[0];
                a0.x = fmaf(v0.x, c0, a0.x); a0.y = fmaf(v0.y, c0, a0.y);
                a0.z = fmaf(v0.z, c0, a0.z); a0.w = fmaf(v0.w, c0, a0.w);
                if (wide) {
                    float4 w0 = x0[32];
                    a1.x = fmaf(w0.x, c0, a1.x); a1.y = fmaf(w0.y, c0, a1.y);
                    a1.z = fmaf(w0.z, c0, a1.z); a1.w = fmaf(w0.w, c0, a1.w);
                }
            }
        }
    }
    float dv = divv ? divv[node] : rsqrtf((float)max(e - s, 1));
    a0.x *= dv; a0.y *= dv; a0.z *= dv; a0.w *= dv;
    size_t o = (size_t)wid * F + lane * 4;
    split4(a0, (__half2*)(oh + o), (__half2*)(ol + o));
    if (wide) {
        a1.x *= dv; a1.y *= dv; a1.z *= dv; a1.w *= dv;
        split4(a1, (__half2*)(oh + o + 128), (__half2*)(ol + o + 128));
    }
}

// half-input variant (L4; F=256 fixed; alist-compacted); emits hi only
__global__ void agg_halfin_kernel(const __half* __restrict__ x,
                                  const float* __restrict__ smul,
                                  const float* __restrict__ divv,
                                  const int* __restrict__ alist,
                                  __half* __restrict__ oh, int nnodes) {
    int wid = (blockIdx.x * blockDim.x + threadIdx.x) >> 5;
    if (wid >= nnodes) return;
    int lane = threadIdx.x & 31;
    int node = alist[wid];
    int s = g_rowstart[node], e = g_rowstart[node + 1];
    float acc[8];
#pragma unroll
    for (int q = 0; q < 8; q++) acc[q] = 0.f;
    for (int b = s; b < e; b += 32) {
        int nn = min(32, e - b);
        int si = 0; float sc = 0.f;
        if (lane < nn) {
            si = g_csrsrc[b + lane];
            sc = smul[si];
        }
        for (int k = 0; k < nn; k++) {
            int sik = __shfl_sync(0xFFFFFFFFu, si, k);
            float sck = __shfl_sync(0xFFFFFFFFu, sc, k);
            if (sck != 0.f) {
                uint4 v = ((const uint4*)x)[(size_t)sik * 32 + lane];  // 8 halves
                const __half2* hp = (const __half2*)&v;
#pragma unroll
                for (int q = 0; q < 4; q++) {
                    float2 f = __half22float2(hp[q]);
                    acc[2 * q]     = fmaf(f.x, sck, acc[2 * q]);
                    acc[2 * q + 1] = fmaf(f.y, sck, acc[2 * q + 1]);
                }
            }
        }
    }
    float dv = divv[node];
    size_t o = (size_t)wid * FH + lane * 8;
    __half2* op = (__half2*)(oh + o);
#pragma unroll
    for (int q = 0; q < 4; q++)
        op[q] = __floats2half2_rn(acc[2 * q] * dv, acc[2 * q + 1] * dv);
}

// final layer: half input gather, fp32 out + bias (F=128)
__global__ void agg_out_kernel(const __half* __restrict__ x, const float* __restrict__ bias,
                               float* __restrict__ out) {
    int wid = (blockIdx.x * blockDim.x + threadIdx.x) >> 5;
    if (wid >= NN) return;
    int lane = threadIdx.x & 31;
    int s = g_rowstart[wid], e = g_rowstart[wid + 1];
    float4 acc = make_float4(0.f, 0.f, 0.f, 0.f);
    for (int b = s; b < e; b += 32) {
        int nn = min(32, e - b);
        int si = 0;
        if (lane < nn) si = g_csrsrc[b + lane];
        for (int k = 0; k < nn; k++) {
            int sik = __shfl_sync(0xFFFFFFFFu, si, k);
            uint2 v = ((const uint2*)x)[(size_t)sik * 32 + lane];  // 4 halves
            float2 f0 = __half22float2(*(const __half2*)&v.x);
            float2 f1 = __half22float2(*(const __half2*)&v.y);
            acc.x += f0.x; acc.y += f0.y; acc.z += f1.x; acc.w += f1.y;
        }
    }
    float dv = rsqrtf((float)max(e - s, 1));
    float4 bb = ((const float4*)bias)[lane];
    acc.x = fmaf(acc.x, dv, bb.x); acc.y = fmaf(acc.y, dv, bb.y);
    acc.z = fmaf(acc.z, dv, bb.z); acc.w = fmaf(acc.w, dv, bb.w);
    ((float4*)out)[(size_t)wid * 32 + lane] = acc;
}

// copy hid1 (fp32) -> xah (fp16) over ACTIVE-1 rows (base for L3's fused skip-add)
__global__ void copyh_kernel(const float* __restrict__ a, const int* __restrict__ alist,
                             __half* __restrict__ o, int nact) {
    int idx = blockIdx.x * blockDim.x + threadIdx.x;
    if (idx >= nact * 64) return;
    int j = idx >> 6, f = idx & 63;
    size_t off = (size_t)alist[j] * 64 + f;
    float4 va = ((const float4*)a)[off];
    __half2 h0 = __floats2half2_rn(va.x, va.y);
    __half2 h1 = __floats2half2_rn(va.z, va.w);
    ((uint2*)o)[off] = make_uint2(*(uint32_t*)&h0, *(uint32_t*)&h1);
}

// ---------------- HMMA fp16-split GEMM (ldmatrix, single-buffer, occ 2) ----
#define SMS 72
#define GEMM_SMEM (4 * 128 * SMS * 2)

#define MMA168(d, a, b) \
    asm volatile( \
        "mma.sync.aligned.m16n8k16.row.col.f32.f16.f16.f32 " \
        "{%0,%1,%2,%3}, {%4,%5,%6,%7}, {%8,%9}, {%0,%1,%2,%3};" \
        : "+f"((d)[0]), "+f"((d)[1]), "+f"((d)[2]), "+f"((d)[3]) \
        : "r"((a)[0]), "r"((a)[1]), "r"((a)[2]), "r"((a)[3]), \
          "r"((b)[0]), "r"((b)[1]))

__device__ __forceinline__ void ldsm4(uint32_t addr, uint32_t* r) {
    asm volatile("ldmatrix.sync.aligned.m8n8.x4.shared.b16 {%0,%1,%2,%3}, [%4];"
                 : "=r"(r[0]), "=r"(r[1]), "=r"(r[2]), "=r"(r[3]) : "r"(addr));
}

// one 64-wide K chunk. NPASS=3: hh+hl+lh. NPASS=1: hh only.
template <int NPASS>
__device__ __forceinline__ void compute_chunk(uint32_t sb, int wm, int wn, int lane,
                                              float acc[4][4][4]) {
    const uint32_t bAh = sb;
    const uint32_t bAl = sb + 128 * SMS * 2;
    const uint32_t bBh = sb + 256 * SMS * 2;
    const uint32_t bBl = sb + 384 * SMS * 2;
    uint32_t aOff = (uint32_t)((wm + (lane & 15)) * SMS + (lane >> 4) * 8) * 2;
    uint32_t bOff = (uint32_t)((wn + ((lane >> 4) & 1) * 8 + (lane & 7)) * SMS +
                               ((lane >> 3) & 1) * 8) * 2;
#pragma unroll
    for (int ks = 0; ks < 4; ks++) {
        uint32_t kb2 = (uint32_t)ks * 32;
        uint32_t ar[4][4], br[4][2], bl[4][2];
#pragma unroll
        for (int mi = 0; mi < 4; mi++)
            ldsm4(bAh + aOff + mi * (16 * SMS * 2) + kb2, ar[mi]);
#pragma unroll
        for (int p = 0; p < 2; p++) {
            uint32_t r4[4];
            ldsm4(bBh + bOff + p * (16 * SMS * 2) + kb2, r4);
            br[2 * p][0] = r4[0]; br[2 * p][1] = r4[1];
            br[2 * p + 1][0] = r4[2]; br[2 * p + 1][1] = r4[3];
            if (NPASS >= 2) {
                ldsm4(bBl + bOff + p * (16 * SMS * 2) + kb2, r4);
                bl[2 * p][0] = r4[0]; bl[2 * p][1] = r4[1];
                bl[2 * p + 1][0] = r4[2]; bl[2 * p + 1][1] = r4[3];
            }
        }
#pragma unroll
        for (int mi = 0; mi < 4; mi++)
#pragma unroll
            for (int ni = 0; ni < 4; ni++) {
                MMA168(acc[mi][ni], ar[mi], br[ni]);
                if (NPASS >= 2) MMA168(acc[mi][ni], ar[mi], bl[ni]);
            }
        if (NPASS >= 3) {
#pragma unroll
            for (int mi = 0; mi < 4; mi++)
                ldsm4(bAl + aOff + mi * (16 * SMS * 2) + kb2, ar[mi]);
#pragma unroll
            for (int mi = 0; mi < 4; mi++)
#pragma unroll
                for (int ni = 0; ni < 4; ni++)
                    MMA168(acc[mi][ni], ar[mi], br[ni]);
        }
    }
}

// AHALF: A pre-split | split-on-load(+add). OUTH: half C. SCORE: score partials.
// ADD: add fp32 addin[grow*N+col] after act (fused decoder skip).
template <int AHALF, int OUTH, int NPASS, int SCORE, int ADD>
__global__ void __launch_bounds__(256, 2)
gemm_kernel(const __half* __restrict__ Ah, const __half* __restrict__ Al,
            const float* __restrict__ A0, const float* __restrict__ A1,
            const __half* __restrict__ Bh, const __half* __restrict__ Bl,
            float* __restrict__ C, int M, int K, int N,
            const int* __restrict__ alist, const float* __restrict__ bias,
            const int* __restrict__ degrm, int act,
            const float* __restrict__ Wp, float* __restrict__ zpart,
            const float* __restrict__ addin) {
    extern __shared__ __half sm[];
    uint32_t smbase = (uint32_t)__cvta_generic_to_shared(sm);
    __half* sAh = sm;
    __half* sAl = sAh + 128 * SMS;
    __half* sBh = sAl + 128 * SMS;
    __half* sBl = sBh + 128 * SMS;
    int t = threadIdx.x;
    int m0 = blockIdx.y * 128, n0 = blockIdx.x * 128;
    int w = t >> 5, lane = t & 31;
    int g = lane >> 2, tig = lane & 3;
    int wm = (w & 1) * 64, wn = (w >> 1) * 32;

    float acc[4][4][4];
#pragma unroll
    for (int i = 0; i < 4; i++)
#pragma unroll
        for (int j = 0; j < 4; j++)
#pragma unroll
            for (int k = 0; k < 4; k++) acc[i][j][k] = 0.f;

    const int NA = (AHALF && NPASS >= 3) ? 2048 : 1024;
    const int NB = (NPASS >= 2) ? 2048 : 1024;
    for (int kc = 0; kc < K; kc += 64) {
        if (AHALF) {
            for (int idx = t; idx < NA; idx += 256) {
                int arr = idx >> 10, j = idx & 1023, r = j >> 3, c = j & 7;
                const __half* srcp = arr ? Al : Ah;
                uint4 v = make_uint4(0, 0, 0, 0);
                if (m0 + r < M) v = *(const uint4*)(srcp + (size_t)(m0 + r) * K + kc + c * 8);
                *(uint4*)((arr ? sAl : sAh) + r * SMS + c * 8) = v;
            }
        } else {
            for (int idx = t; idx < 1024; idx += 256) {
                int r = idx >> 3, c = idx & 7;
                float4 f0 = make_float4(0.f, 0.f, 0.f, 0.f), f1 = f0;
                if (m0 + r < M) {
                    size_t o = (size_t)(m0 + r) * K + kc + c * 8;
                    f0 = *(const float4*)(A0 + o);
                    f1 = *(const float4*)(A0 + o + 4);
                    float4 q0 = *(const float4*)(A1 + o);
                    float4 q1 = *(const float4*)(A1 + o + 4);
                    f0.x += q0.x; f0.y += q0.y; f0.z += q0.z; f0.w += q0.w;
                    f1.x += q1.x; f1.y += q1.y; f1.z += q1.z; f1.w += q1.w;
                }
                __half2 th[2], tl[2];
                split4(f0, th, tl);
                *(__half2*)(sAh + r * SMS + c * 8) = th[0];
                *(__half2*)(sAh + r * SMS + c * 8 + 2) = th[1];
                if (NPASS >= 3) {
                    *(__half2*)(sAl + r * SMS + c * 8) = tl[0];
                    *(__half2*)(sAl + r * SMS + c * 8 + 2) = tl[1];
                }
                split4(f1, th, tl);
                *(__half2*)(sAh + r * SMS + c * 8 + 4) = th[0];
                *(__half2*)(sAh + r * SMS + c * 8 + 6) = th[1];
                if (NPASS >= 3) {
                    *(__half2*)(sAl + r * SMS + c * 8 + 4) = tl[0];
                    *(__half2*)(sAl + r * SMS + c * 8 + 6) = tl[1];
                }
            }
        }
        for (int idx = t; idx < NB; idx += 256) {
            int arr = idx >> 10, j = idx & 1023, r = j >> 3, c = j & 7;
            const __half* srcp = arr ? Bl : Bh;
            uint4 v = *(const uint4*)(srcp + (size_t)(n0 + r) * K + kc + c * 8);
            *(uint4*)((arr ? sBl : sBh) + r * SMS + c * 8) = v;
        }
        __syncthreads();
        compute_chunk<NPASS>(smbase, wm, wn, lane, acc);
        __syncthreads();
    }

    // epilogue (+ optional fused score partials, fused add)
    float wp[4][2];
    if (SCORE) {
#pragma unroll
        for (int ni = 0; ni < 4; ni++) {
            int col = n0 + wn + ni * 8 + tig * 2;
            wp[ni][0] = Wp[col];
            wp[ni][1] = Wp[col + 1];
        }
    }
    float* sZ = (float*)sm;
#pragma unroll
    for (int mi = 0; mi < 4; mi++) {
#pragma unroll
        for (int half8 = 0; half8 < 2; half8++) {
            int lrow = m0 + wm + mi * 16 + g + half8 * 8;
            float zr = 0.f;
            if (lrow < M) {
                int grow = alist ? alist[lrow] : lrow;
                float rm = degrm ? rsqrtf((float)max(degrm[grow], 1)) : 1.f;
#pragma unroll
                for (int ni = 0; ni < 4; ni++) {
                    int col = n0 + wn + ni * 8 + tig * 2;
                    float v0 = acc[mi][ni][half8 * 2 + 0];
                    float v1 = acc[mi][ni][half8 * 2 + 1];
                    if (bias) { v0 += bias[col]; v1 += bias[col + 1]; }
                    if (act) { v0 = fmaxf(v0, 0.f); v1 = fmaxf(v1, 0.f); }
                    v0 *= rm; v1 *= rm;
                    if (SCORE) zr += v0 * wp[ni][0] + v1 * wp[ni][1];
                    if (ADD) {
                        const float2 av = *(const float2*)(addin + (size_t)grow * N + col);
                        v0 += av.x; v1 += av.y;
                    }
                    if (OUTH) {
                        __half2 hv = __floats2half2_rn(v0, v1);
                        *(uint32_t*)((__half*)C + (size_t)grow * N + col) = *(uint32_t*)&hv;
                    } else {
                        *(float2*)(C + (size_t)grow * N + col) = make_float2(v0, v1);
                    }
                }
            }
            if (SCORE) {
                zr += __shfl_xor_sync(0xFFFFFFFFu, zr, 1);
                zr += __shfl_xor_sync(0xFFFFFFFFu, zr, 2);
                if (tig == 0)
                    sZ[(w >> 1) * 128 + wm + mi * 16 + half8 * 8 + g] = zr;
            }
        }
    }
    if (SCORE) {
        __syncthreads();
        if (t < 128 && m0 + t < M) {
            float z = sZ[t] + sZ[128 + t] + sZ[256 + t] + sZ[384 + t];
            int grow = alist ? alist[m0 + t] : m0 + t;
            zpart[grow * 2 + blockIdx.x] = z;
        }
    }
}

// ---------------- pooling: fused key-build + exact top-K radix select ------
__global__ void topk_kernel(int K, int lvl, const float* __restrict__ bp,
                            const float* __restrict__ msk) {
    __shared__ int hist[256];
    __shared__ unsigned s_pref;
    __shared__ int s_kr;
    int tid = threadIdx.x;
    if (tid == 0) { s_pref = 0u; s_kr = K; }
    const int NPAD = ((NN + 1023) / 1024) * 1024;
    float bias0 = bp[0];
    for (int shift = 24; shift >= 0; shift -= 8) {
        if (tid < 256) hist[tid] = 0;
        __syncthreads();
        unsigned pref = s_pref;
        for (int i = tid; i < NPAD; i += 1024) {
            unsigned bucket = 0xFFFFFFFFu;
            if (i < NN) {
                unsigned k;
                if (shift == 24) {
                    float z = g_zpart[2 * i] + g_zpart[2 * i + 1] + bias0;
                    float s = 1.f / (1.f + expf(-z));
                    g_scores[i] = s;
                    float kin = (msk && msk[i] == 0.f) ? -1e9f : s;
                    k = f2k(kin);
                    g_keys[i] = k;
                    bucket = k >> 24;
                } else {
                    k = g_keys[i];
                    if ((k >> (shift + 8)) == (pref >> (shift + 8)))
                        bucket = (k >> shift) & 255u;
                }
            }
            unsigned peers = __match_any_sync(0xFFFFFFFFu, bucket);
            if (bucket != 0xFFFFFFFFu) {
                int leader = __ffs(peers) - 1;
                if ((tid & 31) == leader) atomicAdd(&hist[bucket], __popc(peers));
            }
        }
        __syncthreads();
        if (tid == 0) {
            int kr = s_kr;
            for (int b = 255; b >= 0; b--) {
                int c = hist[b];
                if (c >= kr) { s_pref = pref | (((unsigned)b) << shift); break; }
                kr -= c;
            }
            s_kr = kr;
        }
        __syncthreads();
    }
    if (tid == 0) { g_prefix = s_pref; g_nact[lvl] = 0; }
}

__global__ void degm_kernel(const int* __restrict__ src, const int* __restrict__ dst,
                            int* __restrict__ degO, int* __restrict__ degI) {
    int e = blockIdx.x * blockDim.x + threadIdx.x;
    if (e >= NE) return;
    int s = src[e], d = dst[e];
    if (g_keys[s] >= g_prefix && g_keys[d] >= g_prefix) {
        atomicAdd(&degO[s], 1);
        atomicAdd(&degI[d], 1);
    }
}

__global__ void finact_kernel(const int* __restrict__ degO, const int* __restrict__ degI,
                              float* __restrict__ comb, float* __restrict__ dov,
                              float* __restrict__ divv, int* __restrict__ alist, int lvl) {
    int i = blockIdx.x * blockDim.x + threadIdx.x;
    if (i >= NN) return;
    float mo = rsqrtf((float)max(degO[i], 1));
    bool a = g_keys[i] >= g_prefix;
    comb[i] = a ? g_scores[i] * mo : 0.f;
    dov[i] = a ? mo : 0.f;
    divv[i] = rsqrtf((float)max(degI[i], 1));
    if (a) {
        int p = atomicAdd(&g_nact[lvl], 1);
        alist[p] = i;
    }
}

// ---------------- host orchestration ----------------
static inline void* sym(const void* s) {
    void* p = nullptr;
    cudaGetSymbolAddress(&p, (const void*)s);
    return p;
}

extern "C" void kernel_launch(void* const* d_in, const int* in_sizes, int n_in,
                              void* d_out, int out_size) {
    const float* features = (const float*)d_in[0];
    const int* src = (const int*)d_in[1];
    const int* dst = (const int*)d_in[2];
    const float* W_embed = (const float*)d_in[3];
    const float* b_embed = (const float*)d_in[4];
    const float* W_enc0 = (const float*)d_in[5];
    const float* b_enc0 = (const float*)d_in[6];
    const float* W_enc1 = (const float*)d_in[7];
    const float* b_enc1 = (const float*)d_in[8];
    const float* W_p0 = (const float*)d_in[9];
    const float* b_p0 = (const float*)d_in[10];
    const float* W_p1 = (const float*)d_in[11];
    const float* b_p1 = (const float*)d_in[12];
    const float* W_bot = (const float*)d_in[13];
    const float* b_bot = (const float*)d_in[14];
    const float* W_dec0 = (const float*)d_in[15];
    const float* b_dec0 = (const float*)d_in[16];
    const float* W_dec1 = (const float*)d_in[17];
    const float* b_dec1 = (const float*)d_in[18];
    float* out = (float*)d_out;

    __half* p_xah = (__half*)sym(g_xah);
    float* p_h    = (float*)sym(g_h);
    float* p_hid0 = (float*)sym(g_hid0);
    float* p_hid1 = (float*)sym(g_hid1);
    float* p_h4   = (float*)sym(g_h4);
    __half* p_xh  = (__half*)sym(g_xh);
    __half* p_xl  = (__half*)sym(g_xl);
    __half* p_wth = (__half*)sym(g_wth);
    __half* p_wtl = (__half*)sym(g_wtl);
    float* p_zp   = (float*)sym(g_zpart);
    int* p_degout = (int*)sym(g_degout);
    int* p_degO1  = (int*)sym(g_degO1);
    int* p_degI1  = (int*)sym(g_degI1);
    int* p_degO2  = (int*)sym(g_degO2);
    int* p_degI2  = (int*)sym(g_degI2);
    float* p_comb1 = (float*)sym(g_comb1);
    float* p_dov1  = (float*)sym(g_dov1);
    float* p_div1  = (float*)sym(g_div1);
    float* p_comb2 = (float*)sym(g_comb2);
    float* p_dov2  = (float*)sym(g_dov2);
    float* p_div2  = (float*)sym(g_div2);
    int* p_al1 = (int*)sym(g_alist1);
    int* p_al2 = (int*)sym(g_alist2);

    cudaFuncSetAttribute((const void*)gemm_kernel<1, 0, 3, 0, 0>,
                         cudaFuncAttributeMaxDynamicSharedMemorySize, GEMM_SMEM);
    cudaFuncSetAttribute((const void*)gemm_kernel<1, 0, 3, 1, 0>,
                         cudaFuncAttributeMaxDynamicSharedMemorySize, GEMM_SMEM);
    cudaFuncSetAttribute((const void*)gemm_kernel<1, 1, 1, 0, 1>,
                         cudaFuncAttributeMaxDynamicSharedMemorySize, GEMM_SMEM);
    cudaFuncSetAttribute((const void*)gemm_kernel<1, 0, 1, 0, 0>,
                         cudaFuncAttributeMaxDynamicSharedMemorySize, GEMM_SMEM);
    cudaFuncSetAttribute((const void*)gemm_kernel<0, 1, 1, 0, 0>,
                         cudaFuncAttributeMaxDynamicSharedMemorySize, GEMM_SMEM);

    const int TB = 256;
    const int NB_N = (NN + TB - 1) / TB;
    const int NB_E = (NE + TB - 1) / TB;
    dim3 gFull256(2, (NN + 127) / 128);
    dim3 gFull128(1, (NN + 127) / 128);
    dim3 gK1(2, (K1 + 127) / 128);
    dim3 gK2(2, (K2 + 127) / 128);
    auto wgrid = [](int n) { return (n + 7) / 8; };

    // prep + CSR build
    prep_kernel<<<(327680 + TB - 1) / TB, TB>>>(W_embed, W_enc0, W_enc1, W_bot, W_dec0, W_dec1);
    hist_kernel<<<NB_E, TB>>>(src, dst);
    scan1_kernel<<<NSCAN, 1024>>>();
    scan3_kernel<<<NB_N, TB>>>();
    scatter_kernel<<<NB_E, TB>>>(src, dst);

    // L0 (3-pass: feeds top-k path); branch-free agg
    agg_half_kernel<0><<<wgrid(NN), TB>>>(features, nullptr, p_degout, nullptr, nullptr,
                                          p_xh, p_xl, FI, NN);
    gemm_kernel<1, 0, 3, 0, 0><<<gFull256, 256, GEMM_SMEM>>>(
        p_xh, p_xl, nullptr, nullptr, p_wth + WO_EMB, p_wtl + WO_EMB, p_h,
        NN, FI, FH, nullptr, b_embed, nullptr, 1, nullptr, nullptr, nullptr);

    // L1 (3-pass, fused score partials for pool0)
    agg_half_kernel<0><<<wgrid(NN), TB>>>(p_h, nullptr, p_degout, nullptr, nullptr,
                                          p_xh, p_xl, FH, NN);
    gemm_kernel<1, 0, 3, 1, 0><<<gFull256, 256, GEMM_SMEM>>>(
        p_xh, p_xl, nullptr, nullptr, p_wth + WO_ENC0, p_wtl + WO_ENC0, p_hid0,
        NN, FH, FH, nullptr, b_enc0, nullptr, 1, W_p0, p_zp, nullptr);

    // pool0 (keys fused into topk pass 0)
    topk_kernel<<<1, 1024>>>(K1, 0, b_p0, nullptr);
    degm_kernel<<<NB_E, TB>>>(src, dst, p_degO1, p_degI1);
    finact_kernel<<<NB_N, TB>>>(p_degO1, p_degI1, p_comb1, p_dov1, p_div1, p_al1, 0);

    // L2 (3-pass, fused score partials for pool1)
    agg_half_kernel<1><<<wgrid(K1), TB>>>(p_hid0, p_comb1, nullptr, p_div1, p_al1,
                                          p_xh, p_xl, FH, K1);
    gemm_kernel<1, 0, 3, 1, 0><<<gK1, 256, GEMM_SMEM>>>(
        p_xh, p_xl, nullptr, nullptr, p_wth + WO_ENC1, p_wtl + WO_ENC1, p_hid1,
        K1, FH, FH, p_al1, b_enc1, nullptr, 1, W_p1, p_zp, nullptr);

    // pool1
    topk_kernel<<<1, 1024>>>(K2, 1, b_p1, p_dov1);
    degm_kernel<<<NB_E, TB>>>(src, dst, p_degO2, p_degI2);
    finact_kernel<<<NB_N, TB>>>(p_degO2, p_degI2, p_comb2, p_dov2, p_div2, p_al2, 1);

    // L3 (single-pass fp16): base copy hid1->xah (active-1 rows), GEMM writes
    // relu(out)+hid1 as fp16 directly into xah over its alist2 rows (fused skip-add)
    copyh_kernel<<<(K1 * 64 + TB - 1) / TB, TB>>>(p_hid1, p_al1, p_xah, K1);
    agg_half_kernel<1><<<wgrid(K2), TB>>>(p_hid1, p_comb2, nullptr, p_div2, p_al2,
                                          p_xh, p_xl, FH, K2);
    gemm_kernel<1, 1, 1, 0, 1><<<gK2, 256, GEMM_SMEM>>>(
        p_xh, p_xl, nullptr, nullptr, p_wth + WO_BOT, p_wtl + WO_BOT, (float*)p_xah,
        K2, FH, FH, p_al2, b_bot, nullptr, 1, nullptr, nullptr, p_hid1);

    // L4 (single-pass fp16): half gather over xah, GEMM
    agg_halfin_kernel<<<wgrid(K1), TB>>>(p_xah, p_dov1, p_div1, p_al1, p_xh, K1);
    gemm_kernel<1, 0, 1, 0, 0><<<gK1, 256, GEMM_SMEM>>>(
        p_xh, p_xl, nullptr, nullptr, p_wth + WO_DEC0, p_wtl + WO_DEC0, p_h4,
        K1, FH, FH, p_al1, b_dec0, nullptr, 1, nullptr, nullptr, nullptr);

    // L5 (single-pass fp16): fused (h4+hid0) split-on-load GEMM -> fp16 out; half gather -> out
    gemm_kernel<0, 1, 1, 0, 0><<<gFull128, 256, GEMM_SMEM>>>(
        nullptr, nullptr, p_h4, p_hid0, p_wth + WO_DEC1, p_wtl + WO_DEC1,
        (float*)p_xah, NN, FH, FI, nullptr, nullptr, p_degout, 0,
        nullptr, nullptr, nullptr);
    agg_out_kernel<<<wgrid(NN), TB>>>(p_xah, b_dec1, out);
}

// round 15
// speedup vs baseline: 1.1129x; 1.1129x over previous
#include <cuda_runtime.h>
#include <cuda_fp16.h>
#include <math.h>
#include <stdint.h>

#define NN 50000
#define NE 800000
#define FI 128
#define FH 256
#define K1 25000
#define K2 12500
#define NSCAN 49  // ceil(NN/1024)

// ---------------- scratch (device globals; zero-init, allocation-free) -----
__device__ __align__(16) __half g_xah[NN * FH];  // L4 gather input / L5 gemm out (half)
__device__ __align__(16) float g_h[NN * FH];     // L0 gemm out
__device__ __align__(16) float g_hid0[NN * FH];  // L1 out (full)
__device__ __align__(16) float g_hid1[NN * FH];  // L2 out (scattered; else 0)
__device__ __align__(16) float g_h4[NN * FH];    // L4 out (scattered; else 0)
__device__ __align__(16) __half g_xh[NN * FH];   // gemm A hi
__device__ __align__(16) __half g_xl[NN * FH];   // gemm A lo
__device__ __align__(16) __half g_wth[327680];   // weights hi (transposed)
__device__ __align__(16) __half g_wtl[327680];   // weights lo
__device__ float g_zpart[NN * 2];                // fused score partials
__device__ int g_degout[NN];
__device__ int g_degO1[NN], g_degI1[NN], g_degO2[NN], g_degI2[NN];
__device__ float g_comb1[NN], g_dov1[NN], g_div1[NN];
__device__ float g_comb2[NN], g_dov2[NN], g_div2[NN];
__device__ float g_scores[NN];
__device__ unsigned g_keys[NN];
__device__ int g_rowstart[NN + 1];
__device__ int g_rowoff[NN];
__device__ int g_csrsrc[NE];
__device__ int g_alist1[NN], g_alist2[NN];
__device__ int g_nact[2];
__device__ unsigned g_prefix;
__device__ int g_bsum[64];

#define WO_EMB  0
#define WO_ENC0 32768
#define WO_ENC1 98304
#define WO_BOT  163840
#define WO_DEC0 229376
#define WO_DEC1 294912

__device__ __forceinline__ unsigned f2k(float f) {
    unsigned u = __float_as_uint(f);
    return (u & 0x80000000u) ? ~u : (u | 0x80000000u);
}
__device__ __forceinline__ void split4(float4 v, __half2* ph, __half2* pl) {
    __half h0 = __float2half_rn(v.x), h1 = __float2half_rn(v.y);
    __half h2 = __float2half_rn(v.z), h3 = __float2half_rn(v.w);
    __half l0 = __float2half_rn(v.x - __half2float(h0));
    __half l1 = __float2half_rn(v.y - __half2float(h1));
    __half l2 = __float2half_rn(v.z - __half2float(h2));
    __half l3 = __float2half_rn(v.w - __half2float(h3));
    ph[0] = __halves2half2(h0, h1); ph[1] = __halves2half2(h2, h3);
    pl[0] = __halves2half2(l0, l1); pl[1] = __halves2half2(l2, l3);
}

// ---------------- prep ----------------
__global__ void prep_kernel(const float* __restrict__ We, const float* __restrict__ W0,
                            const float* __restrict__ W1, const float* __restrict__ Wb,
                            const float* __restrict__ Wd0, const float* __restrict__ Wd1) {
    int i = blockIdx.x * blockDim.x + threadIdx.x;
    if (i < NN) {
        g_rowoff[i] = 0; g_degout[i] = 0;
        g_degO1[i] = 0; g_degI1[i] = 0;
        g_degO2[i] = 0; g_degI2[i] = 0;
    }
    if (i == 0) { g_nact[0] = 0; g_nact[1] = 0; g_rowstart[NN] = NE; }
    float w; int o;
    if (i < 32768) {
        int k = i >> 8, n = i & 255;
        w = We[i]; o = WO_EMB + n * 128 + k;
    } else if (i < 98304) {
        int j = i - 32768; int k = j >> 8, n = j & 255;
        w = W0[j]; o = WO_ENC0 + n * 256 + k;
    } else if (i < 163840) {
        int j = i - 98304; int k = j >> 8, n = j & 255;
        w = W1[j]; o = WO_ENC1 + n * 256 + k;
    } else if (i < 229376) {
        int j = i - 163840; int k = j >> 8, n = j & 255;
        w = Wb[j]; o = WO_BOT + n * 256 + k;
    } else if (i < 294912) {
        int j = i - 229376; int k = j >> 8, n = j & 255;
        w = Wd0[j]; o = WO_DEC0 + n * 256 + k;
    } else if (i < 327680) {
        int j = i - 294912; int k = j >> 7, n = j & 127;
        w = Wd1[j]; o = WO_DEC1 + n * 256 + k;
    } else return;
    __half h = __float2half_rn(w);
    g_wth[o] = h;
    g_wtl[o] = __float2half_rn(w - __half2float(h));
}

// ---------------- CSR build ----------------
__global__ void hist_kernel(const int* __restrict__ src, const int* __restrict__ dst) {
    int e = blockIdx.x * blockDim.x + threadIdx.x;
    if (e < NE) {
        atomicAdd(&g_rowoff[dst[e]], 1);
        atomicAdd(&g_degout[src[e]], 1);
    }
}
__global__ void scan1_kernel() {
    int b = blockIdx.x, t = threadIdx.x;
    int i = b * 1024 + t;
    int v = (i < NN) ? g_rowoff[i] : 0;
    int lane = t & 31, wid = t >> 5;
    int x = v;
#pragma unroll
    for (int off = 1; off < 32; off <<= 1) {
        int y = __shfl_up_sync(0xFFFFFFFFu, x, off);
        if (lane >= off) x += y;
    }
    __shared__ int ws[32];
    if (lane == 31) ws[wid] = x;
    __syncthreads();
    if (wid == 0) {
        int y = ws[lane];
#pragma unroll
        for (int off = 1; off < 32; off <<= 1) {
            int z = __shfl_up_sync(0xFFFFFFFFu, y, off);
            if (lane >= off) y += z;
        }
        ws[lane] = y;
    }
    __syncthreads();
    int base = wid ? ws[wid - 1] : 0;
    if (i < NN) g_rowstart[i] = base + x - v;
    if (t == 1023) g_bsum[b] = base + x;
}
__global__ void scan3_kernel() {
    __shared__ int boff[NSCAN + 1];
    int t = threadIdx.x;
    if (t < NSCAN) boff[t + 1] = g_bsum[t];
    __syncthreads();
    if (t == 0) {
        boff[0] = 0;
        for (int b = 1; b <= NSCAN; b++) boff[b] += boff[b - 1];
    }
    __syncthreads();
    int i = blockIdx.x * blockDim.x + t;
    if (i < NN) {
        int rs = g_rowstart[i] + boff[i >> 10];
        g_rowstart[i] = rs;
        g_rowoff[i] = rs;
    }
}
__global__ void scatter_kernel(const int* __restrict__ src, const int* __restrict__ dst) {
    int e = blockIdx.x * blockDim.x + threadIdx.x;
    if (e < NE) {
        int pos = atomicAdd(&g_rowoff[dst[e]], 1);
        g_csrsrc[pos] = src[e];
    }
}

// ---------------- CSR aggregation: 1 warp per node (fp32 input) ----------------
// BR=1: skip zero scales (masked layers). BR=0: branch-free 2-wide unroll.
template <int BR>
__global__ void agg_half_kernel(const float* __restrict__ x,
                                const float* __restrict__ smul, const int* __restrict__ degsrc,
                                const float* __restrict__ divv, const int* __restrict__ alist,
                                __half* __restrict__ oh, __half* __restrict__ ol,
                                int F, int nnodes) {
    int wid = (blockIdx.x * blockDim.x + threadIdx.x) >> 5;
    if (wid >= nnodes) return;
    int lane = threadIdx.x & 31;
    int node = alist ? alist[wid] : wid;
    int s = g_rowstart[node], e = g_rowstart[node + 1];
    int f4 = F >> 2;
    bool wide = (f4 == 64);
    float4 a0 = make_float4(0.f, 0.f, 0.f, 0.f);
    float4 a1 = make_float4(0.f, 0.f, 0.f, 0.f);
    for (int b = s; b < e; b += 32) {
        int nn = min(32, e - b);
        int si = 0; float sc = 0.f;
        if (lane < nn) {
            si = g_csrsrc[b + lane];
            if (smul) sc = smul[si];
            else if (degsrc) sc = rsqrtf((float)max(degsrc[si], 1));
            else sc = 1.f;
        }
        if (BR) {
            for (int k = 0; k < nn; k++) {
                int sik = __shfl_sync(0xFFFFFFFFu, si, k);
                float sck = __shfl_sync(0xFFFFFFFFu, sc, k);
                if (sck != 0.f) {
                    const float4* xp = (const float4*)x + (size_t)sik * f4 + lane;
                    float4 v = xp[0];
                    a0.x = fmaf(v.x, sck, a0.x); a0.y = fmaf(v.y, sck, a0.y);
                    a0.z = fmaf(v.z, sck, a0.z); a0.w = fmaf(v.w, sck, a0.w);
                    if (wide) {
                        float4 v1 = xp[32];
                        a1.x = fmaf(v1.x, sck, a1.x); a1.y = fmaf(v1.y, sck, a1.y);
                        a1.z = fmaf(v1.z, sck, a1.z); a1.w = fmaf(v1.w, sck, a1.w);
                    }
                }
            }
        } else {
            int k = 0;
            for (; k + 2 <= nn; k += 2) {
                int s0 = __shfl_sync(0xFFFFFFFFu, si, k);
                int s1 = __shfl_sync(0xFFFFFFFFu, si, k + 1);
                float c0 = __shfl_sync(0xFFFFFFFFu, sc, k);
                float c1 = __shfl_sync(0xFFFFFFFFu, sc, k + 1);
                const float4* x0 = (const float4*)x + (size_t)s0 * f4 + lane;
                const float4* x1 = (const float4*)x + (size_t)s1 * f4 + lane;
                float4 v0 = x0[0];
                float4 v1 = x1[0];
                a0.x = fmaf(v0.x, c0, a0.x); a0.y = fmaf(v0.y, c0, a0.y);
                a0.z = fmaf(v0.z, c0, a0.z); a0.w = fmaf(v0.w, c0, a0.w);
                a0.x = fmaf(v1.x, c1, a0.x); a0.y = fmaf(v1.y, c1, a0.y);
                a0.z = fmaf(v1.z, c1, a0.z); a0.w = fmaf(v1.w, c1, a0.w);
                if (wide) {
                    float4 w0 = x0[32];
                    float4 w1 = x1[32];
                    a1.x = fmaf(w0.x, c0, a1.x); a1.y = fmaf(w0.y, c0, a1.y);
                    a1.z = fmaf(w0.z, c0, a1.z); a1.w = fmaf(w0.w, c0, a1.w);
                    a1.x = fmaf(w1.x, c1, a1.x); a1.y = fmaf(w1.y, c1, a1.y);
                    a1.z = fmaf(w1.z, c1, a1.z); a1.w = fmaf(w1.w, c1, a1.w);
                }
            }
            if (k < nn) {
                int s0 = __shfl_sync(0xFFFFFFFFu, si, k);
                float c0 = __shfl_sync(0xFFFFFFFFu, sc, k);
                const float4* x0 = (const float4*)x + (size_t)s0 * f4 + lane;
                float4 v0 = x0[0];
                a0.x = fmaf(v0.x, c0, a0.x); a0.y = fmaf(v0.y, c0, a0.y);
                a0.z = fmaf(v0.z, c0, a0.z); a0.w = fmaf(v0.w, c0, a0.w);
                if (wide) {
                    float4 w0 = x0[32];
                    a1.x = fmaf(w0.x, c0, a1.x); a1.y = fmaf(w0.y, c0, a1.y);
                    a1.z = fmaf(w0.z, c0, a1.z); a1.w = fmaf(w0.w, c0, a1.w);
                }
            }
        }
    }
    float dv = divv ? divv[node] : rsqrtf((float)max(e - s, 1));
    a0.x *= dv; a0.y *= dv; a0.z *= dv; a0.w *= dv;
    size_t o = (size_t)wid * F + lane * 4;
    split4(a0, (__half2*)(oh + o), (__half2*)(ol + o));
    if (wide) {
        a1.x *= dv; a1.y *= dv; a1.z *= dv; a1.w *= dv;
        split4(a1, (__half2*)(oh + o + 128), (__half2*)(ol + o + 128));
    }
}

// half-input variant (L4; F=256 fixed; alist-compacted); emits hi only
__global__ void agg_halfin_kernel(const __half* __restrict__ x,
                                  const float* __restrict__ smul,
                                  const float* __restrict__ divv,
                                  const int* __restrict__ alist,
                                  __half* __restrict__ oh, int nnodes) {
    int wid = (blockIdx.x * blockDim.x + threadIdx.x) >> 5;
    if (wid >= nnodes) return;
    int lane = threadIdx.x & 31;
    int node = alist[wid];
    int s = g_rowstart[node], e = g_rowstart[node + 1];
    float acc[8];
#pragma unroll
    for (int q = 0; q < 8; q++) acc[q] = 0.f;
    for (int b = s; b < e; b += 32) {
        int nn = min(32, e - b);
        int si = 0; float sc = 0.f;
        if (lane < nn) {
            si = g_csrsrc[b + lane];
            sc = smul[si];
        }
        for (int k = 0; k < nn; k++) {
            int sik = __shfl_sync(0xFFFFFFFFu, si, k);
            float sck = __shfl_sync(0xFFFFFFFFu, sc, k);
            if (sck != 0.f) {
                uint4 v = ((const uint4*)x)[(size_t)sik * 32 + lane];  // 8 halves
                const __half2* hp = (const __half2*)&v;
#pragma unroll
                for (int q = 0; q < 4; q++) {
                    float2 f = __half22float2(hp[q]);
                    acc[2 * q]     = fmaf(f.x, sck, acc[2 * q]);
                    acc[2 * q + 1] = fmaf(f.y, sck, acc[2 * q + 1]);
                }
            }
        }
    }
    float dv = divv[node];
    size_t o = (size_t)wid * FH + lane * 8;
    __half2* op = (__half2*)(oh + o);
#pragma unroll
    for (int q = 0; q < 4; q++)
        op[q] = __floats2half2_rn(acc[2 * q] * dv, acc[2 * q + 1] * dv);
}

// final layer: half input gather, fp32 out + bias (F=128)
__global__ void agg_out_kernel(const __half* __restrict__ x, const float* __restrict__ bias,
                               float* __restrict__ out) {
    int wid = (blockIdx.x * blockDim.x + threadIdx.x) >> 5;
    if (wid >= NN) return;
    int lane = threadIdx.x & 31;
    int s = g_rowstart[wid], e = g_rowstart[wid + 1];
    float4 acc = make_float4(0.f, 0.f, 0.f, 0.f);
    for (int b = s; b < e; b += 32) {
        int nn = min(32, e - b);
        int si = 0;
        if (lane < nn) si = g_csrsrc[b + lane];
        for (int k = 0; k < nn; k++) {
            int sik = __shfl_sync(0xFFFFFFFFu, si, k);
            uint2 v = ((const uint2*)x)[(size_t)sik * 32 + lane];  // 4 halves
            float2 f0 = __half22float2(*(const __half2*)&v.x);
            float2 f1 = __half22float2(*(const __half2*)&v.y);
            acc.x += f0.x; acc.y += f0.y; acc.z += f1.x; acc.w += f1.y;
        }
    }
    float dv = rsqrtf((float)max(e - s, 1));
    float4 bb = ((const float4*)bias)[lane];
    acc.x = fmaf(acc.x, dv, bb.x); acc.y = fmaf(acc.y, dv, bb.y);
    acc.z = fmaf(acc.z, dv, bb.z); acc.w = fmaf(acc.w, dv, bb.w);
    ((float4*)out)[(size_t)wid * 32 + lane] = acc;
}

// copy hid1 (fp32) -> xah (fp16) over ACTIVE-1 rows (base for L3's fused skip-add)
__global__ void copyh_kernel(const float* __restrict__ a, const int* __restrict__ alist,
                             __half* __restrict__ o, int nact) {
    int idx = blockIdx.x * blockDim.x + threadIdx.x;
    if (idx >= nact * 64) return;
    int j = idx >> 6, f = idx & 63;
    size_t off = (size_t)alist[j] * 64 + f;
    float4 va = ((const float4*)a)[off];
    __half2 h0 = __floats2half2_rn(va.x, va.y);
    __half2 h1 = __floats2half2_rn(va.z, va.w);
    ((uint2*)o)[off] = make_uint2(*(uint32_t*)&h0, *(uint32_t*)&h1);
}

// ---------------- HMMA fp16-split GEMM (ldmatrix, single-buffer, occ 2) ----
#define SMS 72
#define GEMM_SMEM (4 * 128 * SMS * 2)

#define MMA168(d, a, b) \
    asm volatile( \
        "mma.sync.aligned.m16n8k16.row.col.f32.f16.f16.f32 " \
        "{%0,%1,%2,%3}, {%4,%5,%6,%7}, {%8,%9}, {%0,%1,%2,%3};" \
        : "+f"((d)[0]), "+f"((d)[1]), "+f"((d)[2]), "+f"((d)[3]) \
        : "r"((a)[0]), "r"((a)[1]), "r"((a)[2]), "r"((a)[3]), \
          "r"((b)[0]), "r"((b)[1]))

__device__ __forceinline__ void ldsm4(uint32_t addr, uint32_t* r) {
    asm volatile("ldmatrix.sync.aligned.m8n8.x4.shared.b16 {%0,%1,%2,%3}, [%4];"
                 : "=r"(r[0]), "=r"(r[1]), "=r"(r[2]), "=r"(r[3]) : "r"(addr));
}

// one 64-wide K chunk. NPASS=3: hh+hl+lh. NPASS=1: hh only.
template <int NPASS>
__device__ __forceinline__ void compute_chunk(uint32_t sb, int wm, int wn, int lane,
                                              float acc[4][4][4]) {
    const uint32_t bAh = sb;
    const uint32_t bAl = sb + 128 * SMS * 2;
    const uint32_t bBh = sb + 256 * SMS * 2;
    const uint32_t bBl = sb + 384 * SMS * 2;
    uint32_t aOff = (uint32_t)((wm + (lane & 15)) * SMS + (lane >> 4) * 8) * 2;
    uint32_t bOff = (uint32_t)((wn + ((lane >> 4) & 1) * 8 + (lane & 7)) * SMS +
                               ((lane >> 3) & 1) * 8) * 2;
#pragma unroll
    for (int ks = 0; ks < 4; ks++) {
        uint32_t kb2 = (uint32_t)ks * 32;
        uint32_t ar[4][4], br[4][2], bl[4][2];
#pragma unroll
        for (int mi = 0; mi < 4; mi++)
            ldsm4(bAh + aOff + mi * (16 * SMS * 2) + kb2, ar[mi]);
#pragma unroll
        for (int p = 0; p < 2; p++) {
            uint32_t r4[4];
            ldsm4(bBh + bOff + p * (16 * SMS * 2) + kb2, r4);
            br[2 * p][0] = r4[0]; br[2 * p][1] = r4[1];
            br[2 * p + 1][0] = r4[2]; br[2 * p + 1][1] = r4[3];
            if (NPASS >= 2) {
                ldsm4(bBl + bOff + p * (16 * SMS * 2) + kb2, r4);
                bl[2 * p][0] = r4[0]; bl[2 * p][1] = r4[1];
                bl[2 * p + 1][0] = r4[2]; bl[2 * p + 1][1] = r4[3];
            }
        }
#pragma unroll
        for (int mi = 0; mi < 4; mi++)
#pragma unroll
            for (int ni = 0; ni < 4; ni++) {
                MMA168(acc[mi][ni], ar[mi], br[ni]);
                if (NPASS >= 2) MMA168(acc[mi][ni], ar[mi], bl[ni]);
            }
        if (NPASS >= 3) {
#pragma unroll
            for (int mi = 0; mi < 4; mi++)
                ldsm4(bAl + aOff + mi * (16 * SMS * 2) + kb2, ar[mi]);
#pragma unroll
            for (int mi = 0; mi < 4; mi++)
#pragma unroll
                for (int ni = 0; ni < 4; ni++)
                    MMA168(acc[mi][ni], ar[mi], br[ni]);
        }
    }
}

// AHALF: A pre-split | split-on-load(+add). OUTH: half C. SCORE: score partials.
// ADD: add fp32 addin[grow*N+col] after act (fused decoder skip).
template <int AHALF, int OUTH, int NPASS, int SCORE, int ADD>
__global__ void __launch_bounds__(256, 2)
gemm_kernel(const __half* __restrict__ Ah, const __half* __restrict__ Al,
            const float* __restrict__ A0, const float* __restrict__ A1,
            const __half* __restrict__ Bh, const __half* __restrict__ Bl,
            float* __restrict__ C, int M, int K, int N,
            const int* __restrict__ alist, const float* __restrict__ bias,
            const int* __restrict__ degrm, int act,
            const float* __restrict__ Wp, float* __restrict__ zpart,
            const float* __restrict__ addin) {
    extern __shared__ __half sm[];
    uint32_t smbase = (uint32_t)__cvta_generic_to_shared(sm);
    __half* sAh = sm;
    __half* sAl = sAh + 128 * SMS;
    __half* sBh = sAl + 128 * SMS;
    __half* sBl = sBh + 128 * SMS;
    int t = threadIdx.x;
    int m0 = blockIdx.y * 128, n0 = blockIdx.x * 128;
    int w = t >> 5, lane = t & 31;
    int g = lane >> 2, tig = lane & 3;
    int wm = (w & 1) * 64, wn = (w >> 1) * 32;

    float acc[4][4][4];
#pragma unroll
    for (int i = 0; i < 4; i++)
#pragma unroll
        for (int j = 0; j < 4; j++)
#pragma unroll
            for (int k = 0; k < 4; k++) acc[i][j][k] = 0.f;

    const int NA = (AHALF && NPASS >= 3) ? 2048 : 1024;
    const int NB = (NPASS >= 2) ? 2048 : 1024;
    for (int kc = 0; kc < K; kc += 64) {
        if (AHALF) {
            for (int idx = t; idx < NA; idx += 256) {
                int arr = idx >> 10, j = idx & 1023, r = j >> 3, c = j & 7;
                const __half* srcp = arr ? Al : Ah;
                uint4 v = make_uint4(0, 0, 0, 0);
                if (m0 + r < M) v = *(const uint4*)(srcp + (size_t)(m0 + r) * K + kc + c * 8);
                *(uint4*)((arr ? sAl : sAh) + r * SMS + c * 8) = v;
            }
        } else {
            for (int idx = t; idx < 1024; idx += 256) {
                int r = idx >> 3, c = idx & 7;
                float4 f0 = make_float4(0.f, 0.f, 0.f, 0.f), f1 = f0;
                if (m0 + r < M) {
                    size_t o = (size_t)(m0 + r) * K + kc + c * 8;
                    f0 = *(const float4*)(A0 + o);
                    f1 = *(const float4*)(A0 + o + 4);
                    float4 q0 = *(const float4*)(A1 + o);
                    float4 q1 = *(const float4*)(A1 + o + 4);
                    f0.x += q0.x; f0.y += q0.y; f0.z += q0.z; f0.w += q0.w;
                    f1.x += q1.x; f1.y += q1.y; f1.z += q1.z; f1.w += q1.w;
                }
                __half2 th[2], tl[2];
                split4(f0, th, tl);
                *(__half2*)(sAh + r * SMS + c * 8) = th[0];
                *(__half2*)(sAh + r * SMS + c * 8 + 2) = th[1];
                if (NPASS >= 3) {
                    *(__half2*)(sAl + r * SMS + c * 8) = tl[0];
                    *(__half2*)(sAl + r * SMS + c * 8 + 2) = tl[1];
                }
                split4(f1, th, tl);
                *(__half2*)(sAh + r * SMS + c * 8 + 4) = th[0];
                *(__half2*)(sAh + r * SMS + c * 8 + 6) = th[1];
                if (NPASS >= 3) {
                    *(__half2*)(sAl + r * SMS + c * 8 + 4) = tl[0];
                    *(__half2*)(sAl + r * SMS + c * 8 + 6) = tl[1];
                }
            }
        }
        for (int idx = t; idx < NB; idx += 256) {
            int arr = idx >> 10, j = idx & 1023, r = j >> 3, c = j & 7;
            const __half* srcp = arr ? Bl : Bh;
            uint4 v = *(const uint4*)(srcp + (size_t)(n0 + r) * K + kc + c * 8);
            *(uint4*)((arr ? sBl : sBh) + r * SMS + c * 8) = v;
        }
        __syncthreads();
        compute_chunk<NPASS>(smbase, wm, wn, lane, acc);
        __syncthreads();
    }

    // epilogue (+ optional fused score partials, fused add)
    float wp[4][2];
    if (SCORE) {
#pragma unroll
        for (int ni = 0; ni < 4; ni++) {
            int col = n0 + wn + ni * 8 + tig * 2;
            wp[ni][0] = Wp[col];
            wp[ni][1] = Wp[col + 1];
        }
    }
    float* sZ = (float*)sm;
#pragma unroll
    for (int mi = 0; mi < 4; mi++) {
#pragma unroll
        for (int half8 = 0; half8 < 2; half8++) {
            int lrow = m0 + wm + mi * 16 + g + half8 * 8;
            float zr = 0.f;
            if (lrow < M) {
                int grow = alist ? alist[lrow] : lrow;
                float rm = degrm ? rsqrtf((float)max(degrm[grow], 1)) : 1.f;
#pragma unroll
                for (int ni = 0; ni < 4; ni++) {
                    int col = n0 + wn + ni * 8 + tig * 2;
                    float v0 = acc[mi][ni][half8 * 2 + 0];
                    float v1 = acc[mi][ni][half8 * 2 + 1];
                    if (bias) { v0 += bias[col]; v1 += bias[col + 1]; }
                    if (act) { v0 = fmaxf(v0, 0.f); v1 = fmaxf(v1, 0.f); }
                    v0 *= rm; v1 *= rm;
                    if (SCORE) zr += v0 * wp[ni][0] + v1 * wp[ni][1];
                    if (ADD) {
                        const float2 av = *(const float2*)(addin + (size_t)grow * N + col);
                        v0 += av.x; v1 += av.y;
                    }
                    if (OUTH) {
                        __half2 hv = __floats2half2_rn(v0, v1);
                        *(uint32_t*)((__half*)C + (size_t)grow * N + col) = *(uint32_t*)&hv;
                    } else {
                        *(float2*)(C + (size_t)grow * N + col) = make_float2(v0, v1);
                    }
                }
            }
            if (SCORE) {
                zr += __shfl_xor_sync(0xFFFFFFFFu, zr, 1);
                zr += __shfl_xor_sync(0xFFFFFFFFu, zr, 2);
                if (tig == 0)
                    sZ[(w >> 1) * 128 + wm + mi * 16 + half8 * 8 + g] = zr;
            }
        }
    }
    if (SCORE) {
        __syncthreads();
        if (t < 128 && m0 + t < M) {
            float z = sZ[t] + sZ[128 + t] + sZ[256 + t] + sZ[384 + t];
            int grow = alist ? alist[m0 + t] : m0 + t;
            zpart[grow * 2 + blockIdx.x] = z;
        }
    }
}

// ---------------- pooling ----------------
// finish fused scores: z = zpart0 + zpart1 + bias -> sigmoid -> key (parallel)
__global__ void scorekey_kernel(const float* __restrict__ bp, const float* __restrict__ msk) {
    int i = blockIdx.x * blockDim.x + threadIdx.x;
    if (i >= NN) return;
    float z = g_zpart[2 * i] + g_zpart[2 * i + 1] + bp[0];
    float s = 1.f / (1.f + expf(-z));
    g_scores[i] = s;
    float kin = (msk && msk[i] == 0.f) ? -1e9f : s;
    g_keys[i] = f2k(kin);
}

__global__ void topk_kernel(int K, int lvl) {
    __shared__ int hist[256];
    __shared__ unsigned s_pref;
    __shared__ int s_kr;
    int tid = threadIdx.x;
    if (tid == 0) { s_pref = 0u; s_kr = K; }
    const int NPAD = ((NN + 1023) / 1024) * 1024;
    for (int shift = 24; shift >= 0; shift -= 8) {
        if (tid < 256) hist[tid] = 0;
        __syncthreads();
        unsigned pref = s_pref;
        for (int i = tid; i < NPAD; i += 1024) {
            unsigned bucket = 0xFFFFFFFFu;
            if (i < NN) {
                unsigned k = g_keys[i];
                bool ok = (shift == 24) || ((k >> (shift + 8)) == (pref >> (shift + 8)));
                if (ok) bucket = (k >> shift) & 255u;
            }
            unsigned peers = __match_any_sync(0xFFFFFFFFu, bucket);
            if (bucket != 0xFFFFFFFFu) {
                int leader = __ffs(peers) - 1;
                if ((tid & 31) == leader) atomicAdd(&hist[bucket], __popc(peers));
            }
        }
        __syncthreads();
        if (tid == 0) {
            int kr = s_kr;
            for (int b = 255; b >= 0; b--) {
                int c = hist[b];
                if (c >= kr) { s_pref = pref | (((unsigned)b) << shift); break; }
                kr -= c;
            }
            s_kr = kr;
        }
        __syncthreads();
    }
    if (tid == 0) { g_prefix = s_pref; g_nact[lvl] = 0; }
}

__global__ void degm_kernel(const int* __restrict__ src, const int* __restrict__ dst,
                            int* __restrict__ degO, int* __restrict__ degI) {
    int e = blockIdx.x * blockDim.x + threadIdx.x;
    if (e >= NE) return;
    int s = src[e], d = dst[e];
    if (g_keys[s] >= g_prefix && g_keys[d] >= g_prefix) {
        atomicAdd(&degO[s], 1);
        atomicAdd(&degI[d], 1);
    }
}

__global__ void finact_kernel(const int* __restrict__ degO, const int* __restrict__ degI,
                              float* __restrict__ comb, float* __restrict__ dov,
                              float* __restrict__ divv, int* __restrict__ alist, int lvl) {
    int i = blockIdx.x * blockDim.x + threadIdx.x;
    if (i >= NN) return;
    float mo = rsqrtf((float)max(degO[i], 1));
    bool a = g_keys[i] >= g_prefix;
    comb[i] = a ? g_scores[i] * mo : 0.f;
    dov[i] = a ? mo : 0.f;
    divv[i] = rsqrtf((float)max(degI[i], 1));
    if (a) {
        int p = atomicAdd(&g_nact[lvl], 1);
        alist[p] = i;
    }
}

// ---------------- host orchestration ----------------
static inline void* sym(const void* s) {
    void* p = nullptr;
    cudaGetSymbolAddress(&p, (const void*)s);
    return p;
}

extern "C" void kernel_launch(void* const* d_in, const int* in_sizes, int n_in,
                              void* d_out, int out_size) {
    const float* features = (const float*)d_in[0];
    const int* src = (const int*)d_in[1];
    const int* dst = (const int*)d_in[2];
    const float* W_embed = (const float*)d_in[3];
    const float* b_embed = (const float*)d_in[4];
    const float* W_enc0 = (const float*)d_in[5];
    const float* b_enc0 = (const float*)d_in[6];
    const float* W_enc1 = (const float*)d_in[7];
    const float* b_enc1 = (const float*)d_in[8];
    const float* W_p0 = (const float*)d_in[9];
    const float* b_p0 = (const float*)d_in[10];
    const float* W_p1 = (const float*)d_in[11];
    const float* b_p1 = (const float*)d_in[12];
    const float* W_bot = (const float*)d_in[13];
    const float* b_bot = (const float*)d_in[14];
    const float* W_dec0 = (const float*)d_in[15];
    const float* b_dec0 = (const float*)d_in[16];
    const float* W_dec1 = (const float*)d_in[17];
    const float* b_dec1 = (const float*)d_in[18];
    float* out = (float*)d_out;

    __half* p_xah = (__half*)sym(g_xah);
    float* p_h    = (float*)sym(g_h);
    float* p_hid0 = (float*)sym(g_hid0);
    float* p_hid1 = (float*)sym(g_hid1);
    float* p_h4   = (float*)sym(g_h4);
    __half* p_xh  = (__half*)sym(g_xh);
    __half* p_xl  = (__half*)sym(g_xl);
    __half* p_wth = (__half*)sym(g_wth);
    __half* p_wtl = (__half*)sym(g_wtl);
    float* p_zp   = (float*)sym(g_zpart);
    int* p_degout = (int*)sym(g_degout);
    int* p_degO1  = (int*)sym(g_degO1);
    int* p_degI1  = (int*)sym(g_degI1);
    int* p_degO2  = (int*)sym(g_degO2);
    int* p_degI2  = (int*)sym(g_degI2);
    float* p_comb1 = (float*)sym(g_comb1);
    float* p_dov1  = (float*)sym(g_dov1);
    float* p_div1  = (float*)sym(g_div1);
    float* p_comb2 = (float*)sym(g_comb2);
    float* p_dov2  = (float*)sym(g_dov2);
    float* p_div2  = (float*)sym(g_div2);
    int* p_al1 = (int*)sym(g_alist1);
    int* p_al2 = (int*)sym(g_alist2);

    cudaFuncSetAttribute((const void*)gemm_kernel<1, 0, 3, 0, 0>,
                         cudaFuncAttributeMaxDynamicSharedMemorySize, GEMM_SMEM);
    cudaFuncSetAttribute((const void*)gemm_kernel<1, 0, 3, 1, 0>,
                         cudaFuncAttributeMaxDynamicSharedMemorySize, GEMM_SMEM);
    cudaFuncSetAttribute((const void*)gemm_kernel<1, 1, 1, 0, 1>,
                         cudaFuncAttributeMaxDynamicSharedMemorySize, GEMM_SMEM);
    cudaFuncSetAttribute((const void*)gemm_kernel<1, 0, 1, 0, 0>,
                         cudaFuncAttributeMaxDynamicSharedMemorySize, GEMM_SMEM);
    cudaFuncSetAttribute((const void*)gemm_kernel<0, 1, 1, 0, 0>,
                         cudaFuncAttributeMaxDynamicSharedMemorySize, GEMM_SMEM);

    const int TB = 256;
    const int NB_N = (NN + TB - 1) / TB;
    const int NB_E = (NE + TB - 1) / TB;
    dim3 gFull256(2, (NN + 127) / 128);
    dim3 gFull128(1, (NN + 127) / 128);
    dim3 gK1(2, (K1 + 127) / 128);
    dim3 gK2(2, (K2 + 127) / 128);
    auto wgrid = [](int n) { return (n + 7) / 8; };

    // prep + CSR build
    prep_kernel<<<(327680 + TB - 1) / TB, TB>>>(W_embed, W_enc0, W_enc1, W_bot, W_dec0, W_dec1);
    hist_kernel<<<NB_E, TB>>>(src, dst);
    scan1_kernel<<<NSCAN, 1024>>>();
    scan3_kernel<<<NB_N, TB>>>();
    scatter_kernel<<<NB_E, TB>>>(src, dst);

    // L0 (3-pass: feeds top-k path); branch-free agg
    agg_half_kernel<0><<<wgrid(NN), TB>>>(features, nullptr, p_degout, nullptr, nullptr,
                                          p_xh, p_xl, FI, NN);
    gemm_kernel<1, 0, 3, 0, 0><<<gFull256, 256, GEMM_SMEM>>>(
        p_xh, p_xl, nullptr, nullptr, p_wth + WO_EMB, p_wtl + WO_EMB, p_h,
        NN, FI, FH, nullptr, b_embed, nullptr, 1, nullptr, nullptr, nullptr);

    // L1 (3-pass, fused score partials for pool0)
    agg_half_kernel<0><<<wgrid(NN), TB>>>(p_h, nullptr, p_degout, nullptr, nullptr,
                                          p_xh, p_xl, FH, NN);
    gemm_kernel<1, 0, 3, 1, 0><<<gFull256, 256, GEMM_SMEM>>>(
        p_xh, p_xl, nullptr, nullptr, p_wth + WO_ENC0, p_wtl + WO_ENC0, p_hid0,
        NN, FH, FH, nullptr, b_enc0, nullptr, 1, W_p0, p_zp, nullptr);

    // pool0 (parallel scorekey, then pure topk)
    scorekey_kernel<<<NB_N, TB>>>(b_p0, nullptr);
    topk_kernel<<<1, 1024>>>(K1, 0);
    degm_kernel<<<NB_E, TB>>>(src, dst, p_degO1, p_degI1);
    finact_kernel<<<NB_N, TB>>>(p_degO1, p_degI1, p_comb1, p_dov1, p_div1, p_al1, 0);

    // L2 (3-pass, fused score partials for pool1)
    agg_half_kernel<1><<<wgrid(K1), TB>>>(p_hid0, p_comb1, nullptr, p_div1, p_al1,
                                          p_xh, p_xl, FH, K1);
    gemm_kernel<1, 0, 3, 1, 0><<<gK1, 256, GEMM_SMEM>>>(
        p_xh, p_xl, nullptr, nullptr, p_wth + WO_ENC1, p_wtl + WO_ENC1, p_hid1,
        K1, FH, FH, p_al1, b_enc1, nullptr, 1, W_p1, p_zp, nullptr);

    // pool1
    scorekey_kernel<<<NB_N, TB>>>(b_p1, p_dov1);
    topk_kernel<<<1, 1024>>>(K2, 1);
    degm_kernel<<<NB_E, TB>>>(src, dst, p_degO2, p_degI2);
    finact_kernel<<<NB_N, TB>>>(p_degO2, p_degI2, p_comb2, p_dov2, p_div2, p_al2, 1);

    // L3 (single-pass fp16): base copy hid1->xah (active-1 rows), GEMM writes
    // relu(out)+hid1 as fp16 directly into xah over its alist2 rows (fused skip-add)
    copyh_kernel<<<(K1 * 64 + TB - 1) / TB, TB>>>(p_hid1, p_al1, p_xah, K1);
    agg_half_kernel<1><<<wgrid(K2), TB>>>(p_hid1, p_comb2, nullptr, p_div2, p_al2,
                                          p_xh, p_xl, FH, K2);
    gemm_kernel<1, 1, 1, 0, 1><<<gK2, 256, GEMM_SMEM>>>(
        p_xh, p_xl, nullptr, nullptr, p_wth + WO_BOT, p_wtl + WO_BOT, (float*)p_xah,
        K2, FH, FH, p_al2, b_bot, nullptr, 1, nullptr, nullptr, p_hid1);

    // L4 (single-pass fp16): half gather over xah, GEMM
    agg_halfin_kernel<<<wgrid(K1), TB>>>(p_xah, p_dov1, p_div1, p_al1, p_xh, K1);
    gemm_kernel<1, 0, 1, 0, 0><<<gK1, 256, GEMM_SMEM>>>(
        p_xh, p_xl, nullptr, nullptr, p_wth + WO_DEC0, p_wtl + WO_DEC0, p_h4,
        K1, FH, FH, p_al1, b_dec0, nullptr, 1, nullptr, nullptr, nullptr);

    // L5 (single-pass fp16): fused (h4+hid0) split-on-load GEMM -> fp16 out; half gather -> out
    gemm_kernel<0, 1, 1, 0, 0><<<gFull128, 256, GEMM_SMEM>>>(
        nullptr, nullptr, p_h4, p_hid0, p_wth + WO_DEC1, p_wtl + WO_DEC1,
        (float*)p_xah, NN, FH, FI, nullptr, nullptr, p_degout, 0,
        nullptr, nullptr, nullptr);
    agg_out_kernel<<<wgrid(NN), TB>>>(p_xah, b_dec1, out);
}

// round 16
// speedup vs baseline: 1.1351x; 1.0199x over previous
#include <cuda_runtime.h>
#include <cuda_fp16.h>
#include <math.h>
#include <stdint.h>

#define NN 50000
#define NE 800000
#define FI 128
#define FH 256
#define K1 25000
#define K2 12500
#define NSCAN 49  // ceil(NN/1024)

// ---------------- scratch (device globals; zero-init, allocation-free) -----
__device__ __align__(16) __half g_xah[NN * FH];  // L2 out (fp16) / L3 skip-fused / L4 in / L5 out
__device__ __align__(16) float g_h[NN * FH];     // L0 gemm out
__device__ __align__(16) float g_hid0[NN * FH];  // L1 out (full)
__device__ __align__(16) float g_h4[NN * FH];    // L4 out (scattered; else 0)
__device__ __align__(16) __half g_xh[NN * FH];   // gemm A hi
__device__ __align__(16) __half g_xl[NN * FH];   // gemm A lo
__device__ __align__(16) __half g_wth[327680];   // weights hi (transposed)
__device__ __align__(16) __half g_wtl[327680];   // weights lo
__device__ float g_zpart[NN * 2];                // fused score partials
__device__ int g_degout[NN];
__device__ int g_degO1[NN], g_degI1[NN], g_degO2[NN], g_degI2[NN];
__device__ float g_comb1[NN], g_dov1[NN], g_div1[NN];
__device__ float g_comb2[NN], g_dov2[NN], g_div2[NN];
__device__ float g_scores[NN];
__device__ unsigned g_keys[NN];
__device__ int g_rowstart[NN + 1];
__device__ int g_rowoff[NN];
__device__ int g_csrsrc[NE];
__device__ int g_alist1[NN], g_alist2[NN];
__device__ int g_nact[2];
__device__ unsigned g_prefix;
__device__ int g_bsum[64];

#define WO_EMB  0
#define WO_ENC0 32768
#define WO_ENC1 98304
#define WO_BOT  163840
#define WO_DEC0 229376
#define WO_DEC1 294912

__device__ __forceinline__ unsigned f2k(float f) {
    unsigned u = __float_as_uint(f);
    return (u & 0x80000000u) ? ~u : (u | 0x80000000u);
}
__device__ __forceinline__ void split4(float4 v, __half2* ph, __half2* pl) {
    __half h0 = __float2half_rn(v.x), h1 = __float2half_rn(v.y);
    __half h2 = __float2half_rn(v.z), h3 = __float2half_rn(v.w);
    __half l0 = __float2half_rn(v.x - __half2float(h0));
    __half l1 = __float2half_rn(v.y - __half2float(h1));
    __half l2 = __float2half_rn(v.z - __half2float(h2));
    __half l3 = __float2half_rn(v.w - __half2float(h3));
    ph[0] = __halves2half2(h0, h1); ph[1] = __halves2half2(h2, h3);
    pl[0] = __halves2half2(l0, l1); pl[1] = __halves2half2(l2, l3);
}

// ---------------- prep ----------------
__global__ void prep_kernel(const float* __restrict__ We, const float* __restrict__ W0,
                            const float* __restrict__ W1, const float* __restrict__ Wb,
                            const float* __restrict__ Wd0, const float* __restrict__ Wd1) {
    int i = blockIdx.x * blockDim.x + threadIdx.x;
    if (i < NN) {
        g_rowoff[i] = 0; g_degout[i] = 0;
        g_degO1[i] = 0; g_degI1[i] = 0;
        g_degO2[i] = 0; g_degI2[i] = 0;
    }
    if (i == 0) { g_nact[0] = 0; g_nact[1] = 0; g_rowstart[NN] = NE; }
    float w; int o;
    if (i < 32768) {
        int k = i >> 8, n = i & 255;
        w = We[i]; o = WO_EMB + n * 128 + k;
    } else if (i < 98304) {
        int j = i - 32768; int k = j >> 8, n = j & 255;
        w = W0[j]; o = WO_ENC0 + n * 256 + k;
    } else if (i < 163840) {
        int j = i - 98304; int k = j >> 8, n = j & 255;
        w = W1[j]; o = WO_ENC1 + n * 256 + k;
    } else if (i < 229376) {
        int j = i - 163840; int k = j >> 8, n = j & 255;
        w = Wb[j]; o = WO_BOT + n * 256 + k;
    } else if (i < 294912) {
        int j = i - 229376; int k = j >> 8, n = j & 255;
        w = Wd0[j]; o = WO_DEC0 + n * 256 + k;
    } else if (i < 327680) {
        int j = i - 294912; int k = j >> 7, n = j & 127;
        w = Wd1[j]; o = WO_DEC1 + n * 256 + k;
    } else return;
    __half h = __float2half_rn(w);
    g_wth[o] = h;
    g_wtl[o] = __float2half_rn(w - __half2float(h));
}

// ---------------- CSR build ----------------
__global__ void hist_kernel(const int* __restrict__ src, const int* __restrict__ dst) {
    int e = blockIdx.x * blockDim.x + threadIdx.x;
    if (e < NE) {
        atomicAdd(&g_rowoff[dst[e]], 1);
        atomicAdd(&g_degout[src[e]], 1);
    }
}
__global__ void scan1_kernel() {
    int b = blockIdx.x, t = threadIdx.x;
    int i = b * 1024 + t;
    int v = (i < NN) ? g_rowoff[i] : 0;
    int lane = t & 31, wid = t >> 5;
    int x = v;
#pragma unroll
    for (int off = 1; off < 32; off <<= 1) {
        int y = __shfl_up_sync(0xFFFFFFFFu, x, off);
        if (lane >= off) x += y;
    }
    __shared__ int ws[32];
    if (lane == 31) ws[wid] = x;
    __syncthreads();
    if (wid == 0) {
        int y = ws[lane];
#pragma unroll
        for (int off = 1; off < 32; off <<= 1) {
            int z = __shfl_up_sync(0xFFFFFFFFu, y, off);
            if (lane >= off) y += z;
        }
        ws[lane] = y;
    }
    __syncthreads();
    int base = wid ? ws[wid - 1] : 0;
    if (i < NN) g_rowstart[i] = base + x - v;
    if (t == 1023) g_bsum[b] = base + x;
}
__global__ void scan3_kernel() {
    __shared__ int boff[NSCAN + 1];
    int t = threadIdx.x;
    if (t < NSCAN) boff[t + 1] = g_bsum[t];
    __syncthreads();
    if (t == 0) {
        boff[0] = 0;
        for (int b = 1; b <= NSCAN; b++) boff[b] += boff[b - 1];
    }
    __syncthreads();
    int i = blockIdx.x * blockDim.x + t;
    if (i < NN) {
        int rs = g_rowstart[i] + boff[i >> 10];
        g_rowstart[i] = rs;
        g_rowoff[i] = rs;
    }
}
__global__ void scatter_kernel(const int* __restrict__ src, const int* __restrict__ dst) {
    int e = blockIdx.x * blockDim.x + threadIdx.x;
    if (e < NE) {
        int pos = atomicAdd(&g_rowoff[dst[e]], 1);
        g_csrsrc[pos] = src[e];
    }
}

// ---------------- CSR aggregation: 1 warp per node (fp32 input) ----------------
// BR=1: skip zero scales (masked layers). BR=0: branch-free 2-wide unroll.
template <int BR>
__global__ void agg_half_kernel(const float* __restrict__ x,
                                const float* __restrict__ smul, const int* __restrict__ degsrc,
                                const float* __restrict__ divv, const int* __restrict__ alist,
                                __half* __restrict__ oh, __half* __restrict__ ol,
                                int F, int nnodes) {
    int wid = (blockIdx.x * blockDim.x + threadIdx.x) >> 5;
    if (wid >= nnodes) return;
    int lane = threadIdx.x & 31;
    int node = alist ? alist[wid] : wid;
    int s = g_rowstart[node], e = g_rowstart[node + 1];
    int f4 = F >> 2;
    bool wide = (f4 == 64);
    float4 a0 = make_float4(0.f, 0.f, 0.f, 0.f);
    float4 a1 = make_float4(0.f, 0.f, 0.f, 0.f);
    for (int b = s; b < e; b += 32) {
        int nn = min(32, e - b);
        int si = 0; float sc = 0.f;
        if (lane < nn) {
            si = g_csrsrc[b + lane];
            if (smul) sc = smul[si];
            else if (degsrc) sc = rsqrtf((float)max(degsrc[si], 1));
            else sc = 1.f;
        }
        if (BR) {
            for (int k = 0; k < nn; k++) {
                int sik = __shfl_sync(0xFFFFFFFFu, si, k);
                float sck = __shfl_sync(0xFFFFFFFFu, sc, k);
                if (sck != 0.f) {
                    const float4* xp = (const float4*)x + (size_t)sik * f4 + lane;
                    float4 v = xp[0];
                    a0.x = fmaf(v.x, sck, a0.x); a0.y = fmaf(v.y, sck, a0.y);
                    a0.z = fmaf(v.z, sck, a0.z); a0.w = fmaf(v.w, sck, a0.w);
                    if (wide) {
                        float4 v1 = xp[32];
                        a1.x = fmaf(v1.x, sck, a1.x); a1.y = fmaf(v1.y, sck, a1.y);
                        a1.z = fmaf(v1.z, sck, a1.z); a1.w = fmaf(v1.w, sck, a1.w);
                    }
                }
            }
        } else {
            int k = 0;
            for (; k + 2 <= nn; k += 2) {
                int s0 = __shfl_sync(0xFFFFFFFFu, si, k);
                int s1 = __shfl_sync(0xFFFFFFFFu, si, k + 1);
                float c0 = __shfl_sync(0xFFFFFFFFu, sc, k);
                float c1 = __shfl_sync(0xFFFFFFFFu, sc, k + 1);
                const float4* x0 = (const float4*)x + (size_t)s0 * f4 + lane;
                const float4* x1 = (const float4*)x + (size_t)s1 * f4 + lane;
                float4 v0 = x0[0];
                float4 v1 = x1[0];
                a0.x = fmaf(v0.x, c0, a0.x); a0.y = fmaf(v0.y, c0, a0.y);
                a0.z = fmaf(v0.z, c0, a0.z); a0.w = fmaf(v0.w, c0, a0.w);
                a0.x = fmaf(v1.x, c1, a0.x); a0.y = fmaf(v1.y, c1, a0.y);
                a0.z = fmaf(v1.z, c1, a0.z); a0.w = fmaf(v1.w, c1, a0.w);
                if (wide) {
                    float4 w0 = x0[32];
                    float4 w1 = x1[32];
                    a1.x = fmaf(w0.x, c0, a1.x); a1.y = fmaf(w0.y, c0, a1.y);
                    a1.z = fmaf(w0.z, c0, a1.z); a1.w = fmaf(w0.w, c0, a1.w);
                    a1.x = fmaf(w1.x, c1, a1.x); a1.y = fmaf(w1.y, c1, a1.y);
                    a1.z = fmaf(w1.z, c1, a1.z); a1.w = fmaf(w1.w, c1, a1.w);
                }
            }
            if (k < nn) {
                int s0 = __shfl_sync(0xFFFFFFFFu, si, k);
                float c0 = __shfl_sync(0xFFFFFFFFu, sc, k);
                const float4* x0 = (const float4*)x + (size_t)s0 * f4 + lane;
                float4 v0 = x0[0];
                a0.x = fmaf(v0.x, c0, a0.x); a0.y = fmaf(v0.y, c0, a0.y);
                a0.z = fmaf(v0.z, c0, a0.z); a0.w = fmaf(v0.w, c0, a0.w);
                if (wide) {
                    float4 w0 = x0[32];
                    a1.x = fmaf(w0.x, c0, a1.x); a1.y = fmaf(w0.y, c0, a1.y);
                    a1.z = fmaf(w0.z, c0, a1.z); a1.w = fmaf(w0.w, c0, a1.w);
                }
            }
        }
    }
    float dv = divv ? divv[node] : rsqrtf((float)max(e - s, 1));
    a0.x *= dv; a0.y *= dv; a0.z *= dv; a0.w *= dv;
    size_t o = (size_t)wid * F + lane * 4;
    split4(a0, (__half2*)(oh + o), (__half2*)(ol + o));
    if (wide) {
        a1.x *= dv; a1.y *= dv; a1.z *= dv; a1.w *= dv;
        split4(a1, (__half2*)(oh + o + 128), (__half2*)(ol + o + 128));
    }
}

// half-input variant (L3/L4; F=256 fixed; alist-compacted); emits hi only
__global__ void agg_halfin_kernel(const __half* __restrict__ x,
                                  const float* __restrict__ smul,
                                  const float* __restrict__ divv,
                                  const int* __restrict__ alist,
                                  __half* __restrict__ oh, int nnodes) {
    int wid = (blockIdx.x * blockDim.x + threadIdx.x) >> 5;
    if (wid >= nnodes) return;
    int lane = threadIdx.x & 31;
    int node = alist[wid];
    int s = g_rowstart[node], e = g_rowstart[node + 1];
    float acc[8];
#pragma unroll
    for (int q = 0; q < 8; q++) acc[q] = 0.f;
    for (int b = s; b < e; b += 32) {
        int nn = min(32, e - b);
        int si = 0; float sc = 0.f;
        if (lane < nn) {
            si = g_csrsrc[b + lane];
            sc = smul[si];
        }
        for (int k = 0; k < nn; k++) {
            int sik = __shfl_sync(0xFFFFFFFFu, si, k);
            float sck = __shfl_sync(0xFFFFFFFFu, sc, k);
            if (sck != 0.f) {
                uint4 v = ((const uint4*)x)[(size_t)sik * 32 + lane];  // 8 halves
                const __half2* hp = (const __half2*)&v;
#pragma unroll
                for (int q = 0; q < 4; q++) {
                    float2 f = __half22float2(hp[q]);
                    acc[2 * q]     = fmaf(f.x, sck, acc[2 * q]);
                    acc[2 * q + 1] = fmaf(f.y, sck, acc[2 * q + 1]);
                }
            }
        }
    }
    float dv = divv[node];
    size_t o = (size_t)wid * FH + lane * 8;
    __half2* op = (__half2*)(oh + o);
#pragma unroll
    for (int q = 0; q < 4; q++)
        op[q] = __floats2half2_rn(acc[2 * q] * dv, acc[2 * q + 1] * dv);
}

// final layer: half input gather, fp32 out + bias (F=128)
__global__ void agg_out_kernel(const __half* __restrict__ x, const float* __restrict__ bias,
                               float* __restrict__ out) {
    int wid = (blockIdx.x * blockDim.x + threadIdx.x) >> 5;
    if (wid >= NN) return;
    int lane = threadIdx.x & 31;
    int s = g_rowstart[wid], e = g_rowstart[wid + 1];
    float4 acc = make_float4(0.f, 0.f, 0.f, 0.f);
    for (int b = s; b < e; b += 32) {
        int nn = min(32, e - b);
        int si = 0;
        if (lane < nn) si = g_csrsrc[b + lane];
        for (int k = 0; k < nn; k++) {
            int sik = __shfl_sync(0xFFFFFFFFu, si, k);
            uint2 v = ((const uint2*)x)[(size_t)sik * 32 + lane];  // 4 halves
            float2 f0 = __half22float2(*(const __half2*)&v.x);
            float2 f1 = __half22float2(*(const __half2*)&v.y);
            acc.x += f0.x; acc.y += f0.y; acc.z += f1.x; acc.w += f1.y;
        }
    }
    float dv = rsqrtf((float)max(e - s, 1));
    float4 bb = ((const float4*)bias)[lane];
    acc.x = fmaf(acc.x, dv, bb.x); acc.y = fmaf(acc.y, dv, bb.y);
    acc.z = fmaf(acc.z, dv, bb.z); acc.w = fmaf(acc.w, dv, bb.w);
    ((float4*)out)[(size_t)wid * 32 + lane] = acc;
}

// ---------------- HMMA fp16-split GEMM (ldmatrix, single-buffer, occ 2) ----
#define SMS 72
#define GEMM_SMEM (4 * 128 * SMS * 2)

#define MMA168(d, a, b) \
    asm volatile( \
        "mma.sync.aligned.m16n8k16.row.col.f32.f16.f16.f32 " \
        "{%0,%1,%2,%3}, {%4,%5,%6,%7}, {%8,%9}, {%0,%1,%2,%3};" \
        : "+f"((d)[0]), "+f"((d)[1]), "+f"((d)[2]), "+f"((d)[3]) \
        : "r"((a)[0]), "r"((a)[1]), "r"((a)[2]), "r"((a)[3]), \
          "r"((b)[0]), "r"((b)[1]))

__device__ __forceinline__ void ldsm4(uint32_t addr, uint32_t* r) {
    asm volatile("ldmatrix.sync.aligned.m8n8.x4.shared.b16 {%0,%1,%2,%3}, [%4];"
                 : "=r"(r[0]), "=r"(r[1]), "=r"(r[2]), "=r"(r[3]) : "r"(addr));
}

// one 64-wide K chunk. NPASS=3: hh+hl+lh. NPASS=1: hh only.
template <int NPASS>
__device__ __forceinline__ void compute_chunk(uint32_t sb, int wm, int wn, int lane,
                                              float acc[4][4][4]) {
    const uint32_t bAh = sb;
    const uint32_t bAl = sb + 128 * SMS * 2;
    const uint32_t bBh = sb + 256 * SMS * 2;
    const uint32_t bBl = sb + 384 * SMS * 2;
    uint32_t aOff = (uint32_t)((wm + (lane & 15)) * SMS + (lane >> 4) * 8) * 2;
    uint32_t bOff = (uint32_t)((wn + ((lane >> 4) & 1) * 8 + (lane & 7)) * SMS +
                               ((lane >> 3) & 1) * 8) * 2;
#pragma unroll
    for (int ks = 0; ks < 4; ks++) {
        uint32_t kb2 = (uint32_t)ks * 32;
        uint32_t ar[4][4], br[4][2], bl[4][2];
#pragma unroll
        for (int mi = 0; mi < 4; mi++)
            ldsm4(bAh + aOff + mi * (16 * SMS * 2) + kb2, ar[mi]);
#pragma unroll
        for (int p = 0; p < 2; p++) {
            uint32_t r4[4];
            ldsm4(bBh + bOff + p * (16 * SMS * 2) + kb2, r4);
            br[2 * p][0] = r4[0]; br[2 * p][1] = r4[1];
            br[2 * p + 1][0] = r4[2]; br[2 * p + 1][1] = r4[3];
            if (NPASS >= 2) {
                ldsm4(bBl + bOff + p * (16 * SMS * 2) + kb2, r4);
                bl[2 * p][0] = r4[0]; bl[2 * p][1] = r4[1];
                bl[2 * p + 1][0] = r4[2]; bl[2 * p + 1][1] = r4[3];
            }
        }
#pragma unroll
        for (int mi = 0; mi < 4; mi++)
#pragma unroll
            for (int ni = 0; ni < 4; ni++) {
                MMA168(acc[mi][ni], ar[mi], br[ni]);
                if (NPASS >= 2) MMA168(acc[mi][ni], ar[mi], bl[ni]);
            }
        if (NPASS >= 3) {
#pragma unroll
            for (int mi = 0; mi < 4; mi++)
                ldsm4(bAl + aOff + mi * (16 * SMS * 2) + kb2, ar[mi]);
#pragma unroll
            for (int mi = 0; mi < 4; mi++)
#pragma unroll
                for (int ni = 0; ni < 4; ni++)
                    MMA168(acc[mi][ni], ar[mi], br[ni]);
        }
    }
}

// AHALF: A pre-split | split-on-load(+add). OUTH: half C. SCORE: score partials.
// ADDH: add fp16 addin[grow*N+col] after act (fused skip; addin may alias C).
template <int AHALF, int OUTH, int NPASS, int SCORE, int ADDH>
__global__ void __launch_bounds__(256, 2)
gemm_kernel(const __half* __restrict__ Ah, const __half* __restrict__ Al,
            const float* __restrict__ A0, const float* __restrict__ A1,
            const __half* __restrict__ Bh, const __half* __restrict__ Bl,
            float* __restrict__ C, int M, int K, int N,
            const int* __restrict__ alist, const float* __restrict__ bias,
            const int* __restrict__ degrm, int act,
            const float* __restrict__ Wp, float* __restrict__ zpart,
            const __half* __restrict__ addin) {
    extern __shared__ __half sm[];
    uint32_t smbase = (uint32_t)__cvta_generic_to_shared(sm);
    __half* sAh = sm;
    __half* sAl = sAh + 128 * SMS;
    __half* sBh = sAl + 128 * SMS;
    __half* sBl = sBh + 128 * SMS;
    int t = threadIdx.x;
    int m0 = blockIdx.y * 128, n0 = blockIdx.x * 128;
    int w = t >> 5, lane = t & 31;
    int g = lane >> 2, tig = lane & 3;
    int wm = (w & 1) * 64, wn = (w >> 1) * 32;

    float acc[4][4][4];
#pragma unroll
    for (int i = 0; i < 4; i++)
#pragma unroll
        for (int j = 0; j < 4; j++)
#pragma unroll
            for (int k = 0; k < 4; k++) acc[i][j][k] = 0.f;

    const int NA = (AHALF && NPASS >= 3) ? 2048 : 1024;
    const int NB = (NPASS >= 2) ? 2048 : 1024;
    for (int kc = 0; kc < K; kc += 64) {
        if (AHALF) {
            for (int idx = t; idx < NA; idx += 256) {
                int arr = idx >> 10, j = idx & 1023, r = j >> 3, c = j & 7;
                const __half* srcp = arr ? Al : Ah;
                uint4 v = make_uint4(0, 0, 0, 0);
                if (m0 + r < M) v = *(const uint4*)(srcp + (size_t)(m0 + r) * K + kc + c * 8);
                *(uint4*)((arr ? sAl : sAh) + r * SMS + c * 8) = v;
            }
        } else {
            for (int idx = t; idx < 1024; idx += 256) {
                int r = idx >> 3, c = idx & 7;
                float4 f0 = make_float4(0.f, 0.f, 0.f, 0.f), f1 = f0;
                if (m0 + r < M) {
                    size_t o = (size_t)(m0 + r) * K + kc + c * 8;
                    f0 = *(const float4*)(A0 + o);
                    f1 = *(const float4*)(A0 + o + 4);
                    float4 q0 = *(const float4*)(A1 + o);
                    float4 q1 = *(const float4*)(A1 + o + 4);
                    f0.x += q0.x; f0.y += q0.y; f0.z += q0.z; f0.w += q0.w;
                    f1.x += q1.x; f1.y += q1.y; f1.z += q1.z; f1.w += q1.w;
                }
                __half2 th[2], tl[2];
                split4(f0, th, tl);
                *(__half2*)(sAh + r * SMS + c * 8) = th[0];
                *(__half2*)(sAh + r * SMS + c * 8 + 2) = th[1];
                if (NPASS >= 3) {
                    *(__half2*)(sAl + r * SMS + c * 8) = tl[0];
                    *(__half2*)(sAl + r * SMS + c * 8 + 2) = tl[1];
                }
                split4(f1, th, tl);
                *(__half2*)(sAh + r * SMS + c * 8 + 4) = th[0];
                *(__half2*)(sAh + r * SMS + c * 8 + 6) = th[1];
                if (NPASS >= 3) {
                    *(__half2*)(sAl + r * SMS + c * 8 + 4) = tl[0];
                    *(__half2*)(sAl + r * SMS + c * 8 + 6) = tl[1];
                }
            }
        }
        for (int idx = t; idx < NB; idx += 256) {
            int arr = idx >> 10, j = idx & 1023, r = j >> 3, c = j & 7;
            const __half* srcp = arr ? Bl : Bh;
            uint4 v = *(const uint4*)(srcp + (size_t)(n0 + r) * K + kc + c * 8);
            *(uint4*)((arr ? sBl : sBh) + r * SMS + c * 8) = v;
        }
        __syncthreads();
        compute_chunk<NPASS>(smbase, wm, wn, lane, acc);
        __syncthreads();
    }

    // epilogue (+ optional fused score partials, fused half add)
    float wp[4][2];
    if (SCORE) {
#pragma unroll
        for (int ni = 0; ni < 4; ni++) {
            int col = n0 + wn + ni * 8 + tig * 2;
            wp[ni][0] = Wp[col];
            wp[ni][1] = Wp[col + 1];
        }
    }
    float* sZ = (float*)sm;
#pragma unroll
    for (int mi = 0; mi < 4; mi++) {
#pragma unroll
        for (int half8 = 0; half8 < 2; half8++) {
            int lrow = m0 + wm + mi * 16 + g + half8 * 8;
            float zr = 0.f;
            if (lrow < M) {
                int grow = alist ? alist[lrow] : lrow;
                float rm = degrm ? rsqrtf((float)max(degrm[grow], 1)) : 1.f;
#pragma unroll
                for (int ni = 0; ni < 4; ni++) {
                    int col = n0 + wn + ni * 8 + tig * 2;
                    float v0 = acc[mi][ni][half8 * 2 + 0];
                    float v1 = acc[mi][ni][half8 * 2 + 1];
                    if (bias) { v0 += bias[col]; v1 += bias[col + 1]; }
                    if (act) { v0 = fmaxf(v0, 0.f); v1 = fmaxf(v1, 0.f); }
                    v0 *= rm; v1 *= rm;
                    if (SCORE) zr += v0 * wp[ni][0] + v1 * wp[ni][1];
                    if (ADDH) {
                        uint32_t av = *(const uint32_t*)(addin + (size_t)grow * N + col);
                        float2 af = __half22float2(*(__half2*)&av);
                        v0 += af.x; v1 += af.y;
                    }
                    if (OUTH) {
                        __half2 hv = __floats2half2_rn(v0, v1);
                        *(uint32_t*)((__half*)C + (size_t)grow * N + col) = *(uint32_t*)&hv;
                    } else {
                        *(float2*)(C + (size_t)grow * N + col) = make_float2(v0, v1);
                    }
                }
            }
            if (SCORE) {
                zr += __shfl_xor_sync(0xFFFFFFFFu, zr, 1);
                zr += __shfl_xor_sync(0xFFFFFFFFu, zr, 2);
                if (tig == 0)
                    sZ[(w >> 1) * 128 + wm + mi * 16 + half8 * 8 + g] = zr;
            }
        }
    }
    if (SCORE) {
        __syncthreads();
        if (t < 128 && m0 + t < M) {
            float z = sZ[t] + sZ[128 + t] + sZ[256 + t] + sZ[384 + t];
            int grow = alist ? alist[m0 + t] : m0 + t;
            zpart[grow * 2 + blockIdx.x] = z;
        }
    }
}

// ---------------- pooling ----------------
__global__ void scorekey_kernel(const float* __restrict__ bp, const float* __restrict__ msk) {
    int i = blockIdx.x * blockDim.x + threadIdx.x;
    if (i >= NN) return;
    float z = g_zpart[2 * i] + g_zpart[2 * i + 1] + bp[0];
    float s = 1.f / (1.f + expf(-z));
    g_scores[i] = s;
    float kin = (msk && msk[i] == 0.f) ? -1e9f : s;
    g_keys[i] = f2k(kin);
}

__global__ void topk_kernel(int K, int lvl) {
    __shared__ int hist[256];
    __shared__ unsigned s_pref;
    __shared__ int s_kr;
    int tid = threadIdx.x;
    if (tid == 0) { s_pref = 0u; s_kr = K; }
    const int NPAD = ((NN + 1023) / 1024) * 1024;
    for (int shift = 24; shift >= 0; shift -= 8) {
        if (tid < 256) hist[tid] = 0;
        __syncthreads();
        unsigned pref = s_pref;
        for (int i = tid; i < NPAD; i += 1024) {
            unsigned bucket = 0xFFFFFFFFu;
            if (i < NN) {
                unsigned k = g_keys[i];
                bool ok = (shift == 24) || ((k >> (shift + 8)) == (pref >> (shift + 8)));
                if (ok) bucket = (k >> shift) & 255u;
            }
            unsigned peers = __match_any_sync(0xFFFFFFFFu, bucket);
            if (bucket != 0xFFFFFFFFu) {
                int leader = __ffs(peers) - 1;
                if ((tid & 31) == leader) atomicAdd(&hist[bucket], __popc(peers));
            }
        }
        __syncthreads();
        if (tid == 0) {
            int kr = s_kr;
            for (int b = 255; b >= 0; b--) {
                int c = hist[b];
                if (c >= kr) { s_pref = pref | (((unsigned)b) << shift); break; }
                kr -= c;
            }
            s_kr = kr;
        }
        __syncthreads();
    }
    if (tid == 0) { g_prefix = s_pref; g_nact[lvl] = 0; }
}

__global__ void degm_kernel(const int* __restrict__ src, const int* __restrict__ dst,
                            int* __restrict__ degO, int* __restrict__ degI) {
    int e = blockIdx.x * blockDim.x + threadIdx.x;
    if (e >= NE) return;
    int s = src[e], d = dst[e];
    if (g_keys[s] >= g_prefix && g_keys[d] >= g_prefix) {
        atomicAdd(&degO[s], 1);
        atomicAdd(&degI[d], 1);
    }
}

__global__ void finact_kernel(const int* __restrict__ degO, const int* __restrict__ degI,
                              float* __restrict__ comb, float* __restrict__ dov,
                              float* __restrict__ divv, int* __restrict__ alist, int lvl) {
    int i = blockIdx.x * blockDim.x + threadIdx.x;
    if (i >= NN) return;
    float mo = rsqrtf((float)max(degO[i], 1));
    bool a = g_keys[i] >= g_prefix;
    comb[i] = a ? g_scores[i] * mo : 0.f;
    dov[i] = a ? mo : 0.f;
    divv[i] = rsqrtf((float)max(degI[i], 1));
    if (a) {
        int p = atomicAdd(&g_nact[lvl], 1);
        alist[p] = i;
    }
}

// ---------------- host orchestration ----------------
static inline void* sym(const void* s) {
    void* p = nullptr;
    cudaGetSymbolAddress(&p, (const void*)s);
    return p;
}

extern "C" void kernel_launch(void* const* d_in, const int* in_sizes, int n_in,
                              void* d_out, int out_size) {
    const float* features = (const float*)d_in[0];
    const int* src = (const int*)d_in[1];
    const int* dst = (const int*)d_in[2];
    const float* W_embed = (const float*)d_in[3];
    const float* b_embed = (const float*)d_in[4];
    const float* W_enc0 = (const float*)d_in[5];
    const float* b_enc0 = (const float*)d_in[6];
    const float* W_enc1 = (const float*)d_in[7];
    const float* b_enc1 = (const float*)d_in[8];
    const float* W_p0 = (const float*)d_in[9];
    const float* b_p0 = (const float*)d_in[10];
    const float* W_p1 = (const float*)d_in[11];
    const float* b_p1 = (const float*)d_in[12];
    const float* W_bot = (const float*)d_in[13];
    const float* b_bot = (const float*)d_in[14];
    const float* W_dec0 = (const float*)d_in[15];
    const float* b_dec0 = (const float*)d_in[16];
    const float* W_dec1 = (const float*)d_in[17];
    const float* b_dec1 = (const float*)d_in[18];
    float* out = (float*)d_out;

    __half* p_xah = (__half*)sym(g_xah);
    float* p_h    = (float*)sym(g_h);
    float* p_hid0 = (float*)sym(g_hid0);
    float* p_h4   = (float*)sym(g_h4);
    __half* p_xh  = (__half*)sym(g_xh);
    __half* p_xl  = (__half*)sym(g_xl);
    __half* p_wth = (__half*)sym(g_wth);
    __half* p_wtl = (__half*)sym(g_wtl);
    float* p_zp   = (float*)sym(g_zpart);
    int* p_degout = (int*)sym(g_degout);
    int* p_degO1  = (int*)sym(g_degO1);
    int* p_degI1  = (int*)sym(g_degI1);
    int* p_degO2  = (int*)sym(g_degO2);
    int* p_degI2  = (int*)sym(g_degI2);
    float* p_comb1 = (float*)sym(g_comb1);
    float* p_dov1  = (float*)sym(g_dov1);
    float* p_div1  = (float*)sym(g_div1);
    float* p_comb2 = (float*)sym(g_comb2);
    float* p_dov2  = (float*)sym(g_dov2);
    float* p_div2  = (float*)sym(g_div2);
    int* p_al1 = (int*)sym(g_alist1);
    int* p_al2 = (int*)sym(g_alist2);

    cudaFuncSetAttribute((const void*)gemm_kernel<1, 0, 3, 0, 0>,
                         cudaFuncAttributeMaxDynamicSharedMemorySize, GEMM_SMEM);
    cudaFuncSetAttribute((const void*)gemm_kernel<1, 0, 3, 1, 0>,
                         cudaFuncAttributeMaxDynamicSharedMemorySize, GEMM_SMEM);
    cudaFuncSetAttribute((const void*)gemm_kernel<1, 1, 3, 1, 0>,
                         cudaFuncAttributeMaxDynamicSharedMemorySize, GEMM_SMEM);
    cudaFuncSetAttribute((const void*)gemm_kernel<1, 1, 1, 0, 1>,
                         cudaFuncAttributeMaxDynamicSharedMemorySize, GEMM_SMEM);
    cudaFuncSetAttribute((const void*)gemm_kernel<1, 0, 1, 0, 0>,
                         cudaFuncAttributeMaxDynamicSharedMemorySize, GEMM_SMEM);
    cudaFuncSetAttribute((const void*)gemm_kernel<0, 1, 1, 0, 0>,
                         cudaFuncAttributeMaxDynamicSharedMemorySize, GEMM_SMEM);

    const int TB = 256;
    const int NB_N = (NN + TB - 1) / TB;
    const int NB_E = (NE + TB - 1) / TB;
    dim3 gFull256(2, (NN + 127) / 128);
    dim3 gFull128(1, (NN + 127) / 128);
    dim3 gK1(2, (K1 + 127) / 128);
    dim3 gK2(2, (K2 + 127) / 128);
    auto wgrid = [](int n) { return (n + 7) / 8; };

    // prep + CSR build
    prep_kernel<<<(327680 + TB - 1) / TB, TB>>>(W_embed, W_enc0, W_enc1, W_bot, W_dec0, W_dec1);
    hist_kernel<<<NB_E, TB>>>(src, dst);
    scan1_kernel<<<NSCAN, 1024>>>();
    scan3_kernel<<<NB_N, TB>>>();
    scatter_kernel<<<NB_E, TB>>>(src, dst);

    // L0 (3-pass: feeds top-k path); branch-free agg
    agg_half_kernel<0><<<wgrid(NN), TB>>>(features, nullptr, p_degout, nullptr, nullptr,
                                          p_xh, p_xl, FI, NN);
    gemm_kernel<1, 0, 3, 0, 0><<<gFull256, 256, GEMM_SMEM>>>(
        p_xh, p_xl, nullptr, nullptr, p_wth + WO_EMB, p_wtl + WO_EMB, p_h,
        NN, FI, FH, nullptr, b_embed, nullptr, 1, nullptr, nullptr, nullptr);

    // L1 (3-pass, fused score partials for pool0)
    agg_half_kernel<0><<<wgrid(NN), TB>>>(p_h, nullptr, p_degout, nullptr, nullptr,
                                          p_xh, p_xl, FH, NN);
    gemm_kernel<1, 0, 3, 1, 0><<<gFull256, 256, GEMM_SMEM>>>(
        p_xh, p_xl, nullptr, nullptr, p_wth + WO_ENC0, p_wtl + WO_ENC0, p_hid0,
        NN, FH, FH, nullptr, b_enc0, nullptr, 1, W_p0, p_zp, nullptr);

    // pool0 (parallel scorekey, then pure topk)
    scorekey_kernel<<<NB_N, TB>>>(b_p0, nullptr);
    topk_kernel<<<1, 1024>>>(K1, 0);
    degm_kernel<<<NB_E, TB>>>(src, dst, p_degO1, p_degI1);
    finact_kernel<<<NB_N, TB>>>(p_degO1, p_degI1, p_comb1, p_dov1, p_div1, p_al1, 0);

    // L2 (3-pass, fused score partials for pool1) -> fp16 OUT directly into xah.
    // Scores for pool1 use fp32 epilogue values (zpart) — storage precision is
    // post-selection only.
    agg_half_kernel<1><<<wgrid(K1), TB>>>(p_hid0, p_comb1, nullptr, p_div1, p_al1,
                                          p_xh, p_xl, FH, K1);
    gemm_kernel<1, 1, 3, 1, 0><<<gK1, 256, GEMM_SMEM>>>(
        p_xh, p_xl, nullptr, nullptr, p_wth + WO_ENC1, p_wtl + WO_ENC1, (float*)p_xah,
        K1, FH, FH, p_al1, b_enc1, nullptr, 1, W_p1, p_zp, nullptr);

    // pool1
    scorekey_kernel<<<NB_N, TB>>>(b_p1, p_dov1);
    topk_kernel<<<1, 1024>>>(K2, 1);
    degm_kernel<<<NB_E, TB>>>(src, dst, p_degO2, p_degI2);
    finact_kernel<<<NB_N, TB>>>(p_degO2, p_degI2, p_comb2, p_dov2, p_div2, p_al2, 1);

    // L3 (single-pass fp16): gather hid1(fp16, in xah) over m2 subgraph; GEMM
    // writes relu(out)+hid1 back into xah at al2 rows (read-before-write, same thread)
    agg_halfin_kernel<<<wgrid(K2), TB>>>(p_xah, p_comb2, p_div2, p_al2, p_xh, K2);
    gemm_kernel<1, 1, 1, 0, 1><<<gK2, 256, GEMM_SMEM>>>(
        p_xh, p_xl, nullptr, nullptr, p_wth + WO_BOT, p_wtl + WO_BOT, (float*)p_xah,
        K2, FH, FH, p_al2, b_bot, nullptr, 1, nullptr, nullptr, p_xah);

    // L4 (single-pass fp16): half gather over xah, GEMM -> h4 (fp32)
    agg_halfin_kernel<<<wgrid(K1), TB>>>(p_xah, p_dov1, p_div1, p_al1, p_xh, K1);
    gemm_kernel<1, 0, 1, 0, 0><<<gK1, 256, GEMM_SMEM>>>(
        p_xh, p_xl, nullptr, nullptr, p_wth + WO_DEC0, p_wtl + WO_DEC0, p_h4,
        K1, FH, FH, p_al1, b_dec0, nullptr, 1, nullptr, nullptr, nullptr);

    // L5 (single-pass fp16): fused (h4+hid0) split-on-load GEMM -> fp16 out; half gather -> out
    gemm_kernel<0, 1, 1, 0, 0><<<gFull128, 256, GEMM_SMEM>>>(
        nullptr, nullptr, p_h4, p_hid0, p_wth + WO_DEC1, p_wtl + WO_DEC1,
        (float*)p_xah, NN, FH, FI, nullptr, nullptr, p_degout, 0,
        nullptr, nullptr, nullptr);
    agg_out_kernel<<<wgrid(NN), TB>>>(p_xah, b_dec1, out);
}

// round 17
// speedup vs baseline: 1.1418x; 1.0059x over previous
#include <cuda_runtime.h>
#include <cuda_fp16.h>
#include <math.h>
#include <stdint.h>

#define NN 50000
#define NE 800000
#define FI 128
#define FH 256
#define K1 25000
#define K2 12500
#define NSCAN 49  // ceil(NN/1024)

// ---------------- scratch (device globals; zero-init, allocation-free) -----
__device__ __align__(16) __half g_xah[NN * FH];  // L2 out (fp16) / L3 skip-fused / L4 in / L5 out
__device__ __align__(16) float g_h[NN * FH];     // L0 gemm out
__device__ __align__(16) float g_hid0[NN * FH];  // L1 out (full)
__device__ __align__(16) __half g_h4h[NN * FH];  // L4 out (fp16, scattered; else 0)
__device__ __align__(16) __half g_xh[NN * FH];   // gemm A hi
__device__ __align__(16) __half g_xl[NN * FH];   // gemm A lo
__device__ __align__(16) __half g_wth[327680];   // weights hi (transposed)
__device__ __align__(16) __half g_wtl[327680];   // weights lo
__device__ float g_zpart[NN * 2];                // fused score partials
__device__ int g_degout[NN];
__device__ int g_degO1[NN], g_degI1[NN], g_degO2[NN], g_degI2[NN];
__device__ float g_comb1[NN], g_dov1[NN], g_div1[NN];
__device__ float g_comb2[NN], g_dov2[NN], g_div2[NN];
__device__ float g_scores[NN];
__device__ unsigned g_keys[NN];
__device__ int g_rowstart[NN + 1];
__device__ int g_rowoff[NN];
__device__ int g_csrsrc[NE];
__device__ int g_alist1[NN], g_alist2[NN];
__device__ int g_nact[2];
__device__ unsigned g_prefix;
__device__ int g_bsum[64];

#define WO_EMB  0
#define WO_ENC0 32768
#define WO_ENC1 98304
#define WO_BOT  163840
#define WO_DEC0 229376
#define WO_DEC1 294912

__device__ __forceinline__ unsigned f2k(float f) {
    unsigned u = __float_as_uint(f);
    return (u & 0x80000000u) ? ~u : (u | 0x80000000u);
}
__device__ __forceinline__ void split4(float4 v, __half2* ph, __half2* pl) {
    __half h0 = __float2half_rn(v.x), h1 = __float2half_rn(v.y);
    __half h2 = __float2half_rn(v.z), h3 = __float2half_rn(v.w);
    __half l0 = __float2half_rn(v.x - __half2float(h0));
    __half l1 = __float2half_rn(v.y - __half2float(h1));
    __half l2 = __float2half_rn(v.z - __half2float(h2));
    __half l3 = __float2half_rn(v.w - __half2float(h3));
    ph[0] = __halves2half2(h0, h1); ph[1] = __halves2half2(h2, h3);
    pl[0] = __halves2half2(l0, l1); pl[1] = __halves2half2(l2, l3);
}

// ---------------- prep ----------------
__global__ void prep_kernel(const float* __restrict__ We, const float* __restrict__ W0,
                            const float* __restrict__ W1, const float* __restrict__ Wb,
                            const float* __restrict__ Wd0, const float* __restrict__ Wd1) {
    int i = blockIdx.x * blockDim.x + threadIdx.x;
    if (i < NN) {
        g_rowoff[i] = 0; g_degout[i] = 0;
        g_degO1[i] = 0; g_degI1[i] = 0;
        g_degO2[i] = 0; g_degI2[i] = 0;
    }
    if (i == 0) { g_nact[0] = 0; g_nact[1] = 0; g_rowstart[NN] = NE; }
    float w; int o;
    if (i < 32768) {
        int k = i >> 8, n = i & 255;
        w = We[i]; o = WO_EMB + n * 128 + k;
    } else if (i < 98304) {
        int j = i - 32768; int k = j >> 8, n = j & 255;
        w = W0[j]; o = WO_ENC0 + n * 256 + k;
    } else if (i < 163840) {
        int j = i - 98304; int k = j >> 8, n = j & 255;
        w = W1[j]; o = WO_ENC1 + n * 256 + k;
    } else if (i < 229376) {
        int j = i - 163840; int k = j >> 8, n = j & 255;
        w = Wb[j]; o = WO_BOT + n * 256 + k;
    } else if (i < 294912) {
        int j = i - 229376; int k = j >> 8, n = j & 255;
        w = Wd0[j]; o = WO_DEC0 + n * 256 + k;
    } else if (i < 327680) {
        int j = i - 294912; int k = j >> 7, n = j & 127;
        w = Wd1[j]; o = WO_DEC1 + n * 256 + k;
    } else return;
    __half h = __float2half_rn(w);
    g_wth[o] = h;
    g_wtl[o] = __float2half_rn(w - __half2float(h));
}

// ---------------- CSR build ----------------
__global__ void hist_kernel(const int* __restrict__ src, const int* __restrict__ dst) {
    int e = blockIdx.x * blockDim.x + threadIdx.x;
    if (e < NE) {
        atomicAdd(&g_rowoff[dst[e]], 1);
        atomicAdd(&g_degout[src[e]], 1);
    }
}
__global__ void scan1_kernel() {
    int b = blockIdx.x, t = threadIdx.x;
    int i = b * 1024 + t;
    int v = (i < NN) ? g_rowoff[i] : 0;
    int lane = t & 31, wid = t >> 5;
    int x = v;
#pragma unroll
    for (int off = 1; off < 32; off <<= 1) {
        int y = __shfl_up_sync(0xFFFFFFFFu, x, off);
        if (lane >= off) x += y;
    }
    __shared__ int ws[32];
    if (lane == 31) ws[wid] = x;
    __syncthreads();
    if (wid == 0) {
        int y = ws[lane];
#pragma unroll
        for (int off = 1; off < 32; off <<= 1) {
            int z = __shfl_up_sync(0xFFFFFFFFu, y, off);
            if (lane >= off) y += z;
        }
        ws[lane] = y;
    }
    __syncthreads();
    int base = wid ? ws[wid - 1] : 0;
    if (i < NN) g_rowstart[i] = base + x - v;
    if (t == 1023) g_bsum[b] = base + x;
}
__global__ void scan3_kernel() {
    __shared__ int boff[NSCAN + 1];
    int t = threadIdx.x;
    if (t < NSCAN) boff[t + 1] = g_bsum[t];
    __syncthreads();
    if (t == 0) {
        boff[0] = 0;
        for (int b = 1; b <= NSCAN; b++) boff[b] += boff[b - 1];
    }
    __syncthreads();
    int i = blockIdx.x * blockDim.x + t;
    if (i < NN) {
        int rs = g_rowstart[i] + boff[i >> 10];
        g_rowstart[i] = rs;
        g_rowoff[i] = rs;
    }
}
__global__ void scatter_kernel(const int* __restrict__ src, const int* __restrict__ dst) {
    int e = blockIdx.x * blockDim.x + threadIdx.x;
    if (e < NE) {
        int pos = atomicAdd(&g_rowoff[dst[e]], 1);
        g_csrsrc[pos] = src[e];
    }
}

// ---------------- CSR aggregation: 1 warp per node (fp32 input) ----------------
template <int BR>
__global__ void agg_half_kernel(const float* __restrict__ x,
                                const float* __restrict__ smul, const int* __restrict__ degsrc,
                                const float* __restrict__ divv, const int* __restrict__ alist,
                                __half* __restrict__ oh, __half* __restrict__ ol,
                                int F, int nnodes) {
    int wid = (blockIdx.x * blockDim.x + threadIdx.x) >> 5;
    if (wid >= nnodes) return;
    int lane = threadIdx.x & 31;
    int node = alist ? alist[wid] : wid;
    int s = g_rowstart[node], e = g_rowstart[node + 1];
    int f4 = F >> 2;
    bool wide = (f4 == 64);
    float4 a0 = make_float4(0.f, 0.f, 0.f, 0.f);
    float4 a1 = make_float4(0.f, 0.f, 0.f, 0.f);
    for (int b = s; b < e; b += 32) {
        int nn = min(32, e - b);
        int si = 0; float sc = 0.f;
        if (lane < nn) {
            si = g_csrsrc[b + lane];
            if (smul) sc = smul[si];
            else if (degsrc) sc = rsqrtf((float)max(degsrc[si], 1));
            else sc = 1.f;
        }
        if (BR) {
            for (int k = 0; k < nn; k++) {
                int sik = __shfl_sync(0xFFFFFFFFu, si, k);
                float sck = __shfl_sync(0xFFFFFFFFu, sc, k);
                if (sck != 0.f) {
                    const float4* xp = (const float4*)x + (size_t)sik * f4 + lane;
                    float4 v = xp[0];
                    a0.x = fmaf(v.x, sck, a0.x); a0.y = fmaf(v.y, sck, a0.y);
                    a0.z = fmaf(v.z, sck, a0.z); a0.w = fmaf(v.w, sck, a0.w);
                    if (wide) {
                        float4 v1 = xp[32];
                        a1.x = fmaf(v1.x, sck, a1.x); a1.y = fmaf(v1.y, sck, a1.y);
                        a1.z = fmaf(v1.z, sck, a1.z); a1.w = fmaf(v1.w, sck, a1.w);
                    }
                }
            }
        } else {
            int k = 0;
            for (; k + 2 <= nn; k += 2) {
                int s0 = __shfl_sync(0xFFFFFFFFu, si, k);
                int s1 = __shfl_sync(0xFFFFFFFFu, si, k + 1);
                float c0 = __shfl_sync(0xFFFFFFFFu, sc, k);
                float c1 = __shfl_sync(0xFFFFFFFFu, sc, k + 1);
                const float4* x0 = (const float4*)x + (size_t)s0 * f4 + lane;
                const float4* x1 = (const float4*)x + (size_t)s1 * f4 + lane;
                float4 v0 = x0[0];
                float4 v1 = x1[0];
                a0.x = fmaf(v0.x, c0, a0.x); a0.y = fmaf(v0.y, c0, a0.y);
                a0.z = fmaf(v0.z, c0, a0.z); a0.w = fmaf(v0.w, c0, a0.w);
                a0.x = fmaf(v1.x, c1, a0.x); a0.y = fmaf(v1.y, c1, a0.y);
                a0.z = fmaf(v1.z, c1, a0.z); a0.w = fmaf(v1.w, c1, a0.w);
                if (wide) {
                    float4 w0 = x0[32];
                    float4 w1 = x1[32];
                    a1.x = fmaf(w0.x, c0, a1.x); a1.y = fmaf(w0.y, c0, a1.y);
                    a1.z = fmaf(w0.z, c0, a1.z); a1.w = fmaf(w0.w, c0, a1.w);
                    a1.x = fmaf(w1.x, c1, a1.x); a1.y = fmaf(w1.y, c1, a1.y);
                    a1.z = fmaf(w1.z, c1, a1.z); a1.w = fmaf(w1.w, c1, a1.w);
                }
            }
            if (k < nn) {
                int s0 = __shfl_sync(0xFFFFFFFFu, si, k);
                float c0 = __shfl_sync(0xFFFFFFFFu, sc, k);
                const float4* x0 = (const float4*)x + (size_t)s0 * f4 + lane;
                float4 v0 = x0[0];
                a0.x = fmaf(v0.x, c0, a0.x); a0.y = fmaf(v0.y, c0, a0.y);
                a0.z = fmaf(v0.z, c0, a0.z); a0.w = fmaf(v0.w, c0, a0.w);
                if (wide) {
                    float4 w0 = x0[32];
                    a1.x = fmaf(w0.x, c0, a1.x); a1.y = fmaf(w0.y, c0, a1.y);
                    a1.z = fmaf(w0.z, c0, a1.z); a1.w = fmaf(w0.w, c0, a1.w);
                }
            }
        }
    }
    float dv = divv ? divv[node] : rsqrtf((float)max(e - s, 1));
    a0.x *= dv; a0.y *= dv; a0.z *= dv; a0.w *= dv;
    size_t o = (size_t)wid * F + lane * 4;
    split4(a0, (__half2*)(oh + o), (__half2*)(ol + o));
    if (wide) {
        a1.x *= dv; a1.y *= dv; a1.z *= dv; a1.w *= dv;
        split4(a1, (__half2*)(oh + o + 128), (__half2*)(ol + o + 128));
    }
}

// half-input variant (L3/L4; F=256 fixed; alist-compacted); emits hi only
__global__ void agg_halfin_kernel(const __half* __restrict__ x,
                                  const float* __restrict__ smul,
                                  const float* __restrict__ divv,
                                  const int* __restrict__ alist,
                                  __half* __restrict__ oh, int nnodes) {
    int wid = (blockIdx.x * blockDim.x + threadIdx.x) >> 5;
    if (wid >= nnodes) return;
    int lane = threadIdx.x & 31;
    int node = alist[wid];
    int s = g_rowstart[node], e = g_rowstart[node + 1];
    float acc[8];
#pragma unroll
    for (int q = 0; q < 8; q++) acc[q] = 0.f;
    for (int b = s; b < e; b += 32) {
        int nn = min(32, e - b);
        int si = 0; float sc = 0.f;
        if (lane < nn) {
            si = g_csrsrc[b + lane];
            sc = smul[si];
        }
        for (int k = 0; k < nn; k++) {
            int sik = __shfl_sync(0xFFFFFFFFu, si, k);
            float sck = __shfl_sync(0xFFFFFFFFu, sc, k);
            if (sck != 0.f) {
                uint4 v = ((const uint4*)x)[(size_t)sik * 32 + lane];  // 8 halves
                const __half2* hp = (const __half2*)&v;
#pragma unroll
                for (int q = 0; q < 4; q++) {
                    float2 f = __half22float2(hp[q]);
                    acc[2 * q]     = fmaf(f.x, sck, acc[2 * q]);
                    acc[2 * q + 1] = fmaf(f.y, sck, acc[2 * q + 1]);
                }
            }
        }
    }
    float dv = divv[node];
    size_t o = (size_t)wid * FH + lane * 8;
    __half2* op = (__half2*)(oh + o);
#pragma unroll
    for (int q = 0; q < 4; q++)
        op[q] = __floats2half2_rn(acc[2 * q] * dv, acc[2 * q + 1] * dv);
}

// final layer: half input gather, fp32 out + bias (F=128)
__global__ void agg_out_kernel(const __half* __restrict__ x, const float* __restrict__ bias,
                               float* __restrict__ out) {
    int wid = (blockIdx.x * blockDim.x + threadIdx.x) >> 5;
    if (wid >= NN) return;
    int lane = threadIdx.x & 31;
    int s = g_rowstart[wid], e = g_rowstart[wid + 1];
    float4 acc = make_float4(0.f, 0.f, 0.f, 0.f);
    for (int b = s; b < e; b += 32) {
        int nn = min(32, e - b);
        int si = 0;
        if (lane < nn) si = g_csrsrc[b + lane];
        for (int k = 0; k < nn; k++) {
            int sik = __shfl_sync(0xFFFFFFFFu, si, k);
            uint2 v = ((const uint2*)x)[(size_t)sik * 32 + lane];  // 4 halves
            float2 f0 = __half22float2(*(const __half2*)&v.x);
            float2 f1 = __half22float2(*(const __half2*)&v.y);
            acc.x += f0.x; acc.y += f0.y; acc.z += f1.x; acc.w += f1.y;
        }
    }
    float dv = rsqrtf((float)max(e - s, 1));
    float4 bb = ((const float4*)bias)[lane];
    acc.x = fmaf(acc.x, dv, bb.x); acc.y = fmaf(acc.y, dv, bb.y);
    acc.z = fmaf(acc.z, dv, bb.z); acc.w = fmaf(acc.w, dv, bb.w);
    ((float4*)out)[(size_t)wid * 32 + lane] = acc;
}

// ---------------- HMMA fp16-split GEMM (ldmatrix, single-buffer, occ 2) ----
#define SMS 72
#define GEMM_SMEM (4 * 128 * SMS * 2)

#define MMA168(d, a, b) \
    asm volatile( \
        "mma.sync.aligned.m16n8k16.row.col.f32.f16.f16.f32 " \
        "{%0,%1,%2,%3}, {%4,%5,%6,%7}, {%8,%9}, {%0,%1,%2,%3};" \
        : "+f"((d)[0]), "+f"((d)[1]), "+f"((d)[2]), "+f"((d)[3]) \
        : "r"((a)[0]), "r"((a)[1]), "r"((a)[2]), "r"((a)[3]), \
          "r"((b)[0]), "r"((b)[1]))

__device__ __forceinline__ void ldsm4(uint32_t addr, uint32_t* r) {
    asm volatile("ldmatrix.sync.aligned.m8n8.x4.shared.b16 {%0,%1,%2,%3}, [%4];"
                 : "=r"(r[0]), "=r"(r[1]), "=r"(r[2]), "=r"(r[3]) : "r"(addr));
}

template <int NPASS>
__device__ __forceinline__ void compute_chunk(uint32_t sb, int wm, int wn, int lane,
                                              float acc[4][4][4]) {
    const uint32_t bAh = sb;
    const uint32_t bAl = sb + 128 * SMS * 2;
    const uint32_t bBh = sb + 256 * SMS * 2;
    const uint32_t bBl = sb + 384 * SMS * 2;
    uint32_t aOff = (uint32_t)((wm + (lane & 15)) * SMS + (lane >> 4) * 8) * 2;
    uint32_t bOff = (uint32_t)((wn + ((lane >> 4) & 1) * 8 + (lane & 7)) * SMS +
                               ((lane >> 3) & 1) * 8) * 2;
#pragma unroll
    for (int ks = 0; ks < 4; ks++) {
        uint32_t kb2 = (uint32_t)ks * 32;
        uint32_t ar[4][4], br[4][2], bl[4][2];
#pragma unroll
        for (int mi = 0; mi < 4; mi++)
            ldsm4(bAh + aOff + mi * (16 * SMS * 2) + kb2, ar[mi]);
#pragma unroll
        for (int p = 0; p < 2; p++) {
            uint32_t r4[4];
            ldsm4(bBh + bOff + p * (16 * SMS * 2) + kb2, r4);
            br[2 * p][0] = r4[0]; br[2 * p][1] = r4[1];
            br[2 * p + 1][0] = r4[2]; br[2 * p + 1][1] = r4[3];
            if (NPASS >= 2) {
                ldsm4(bBl + bOff + p * (16 * SMS * 2) + kb2, r4);
                bl[2 * p][0] = r4[0]; bl[2 * p][1] = r4[1];
                bl[2 * p + 1][0] = r4[2]; bl[2 * p + 1][1] = r4[3];
            }
        }
#pragma unroll
        for (int mi = 0; mi < 4; mi++)
#pragma unroll
            for (int ni = 0; ni < 4; ni++) {
                MMA168(acc[mi][ni], ar[mi], br[ni]);
                if (NPASS >= 2) MMA168(acc[mi][ni], ar[mi], bl[ni]);
            }
        if (NPASS >= 3) {
#pragma unroll
            for (int mi = 0; mi < 4; mi++)
                ldsm4(bAl + aOff + mi * (16 * SMS * 2) + kb2, ar[mi]);
#pragma unroll
            for (int mi = 0; mi < 4; mi++)
#pragma unroll
                for (int ni = 0; ni < 4; ni++)
                    MMA168(acc[mi][ni], ar[mi], br[ni]);
        }
    }
}

// AHALF: A pre-split | split-on-load(+add). OUTH: half C. SCORE: score partials.
// ADDH: add fp16 addin after act (may alias C). A0H: A0 is fp16 (with AHALF=0).
template <int AHALF, int OUTH, int NPASS, int SCORE, int ADDH, int A0H>
__global__ void __launch_bounds__(256, 2)
gemm_kernel(const __half* __restrict__ Ah, const __half* __restrict__ Al,
            const float* __restrict__ A0, const float* __restrict__ A1,
            const __half* __restrict__ Bh, const __half* __restrict__ Bl,
            float* __restrict__ C, int M, int K, int N,
            const int* __restrict__ alist, const float* __restrict__ bias,
            const int* __restrict__ degrm, int act,
            const float* __restrict__ Wp, float* __restrict__ zpart,
            const __half* __restrict__ addin) {
    extern __shared__ __half sm[];
    uint32_t smbase = (uint32_t)__cvta_generic_to_shared(sm);
    __half* sAh = sm;
    __half* sAl = sAh + 128 * SMS;
    __half* sBh = sAl + 128 * SMS;
    __half* sBl = sBh + 128 * SMS;
    int t = threadIdx.x;
    int m0 = blockIdx.y * 128, n0 = blockIdx.x * 128;
    int w = t >> 5, lane = t & 31;
    int g = lane >> 2, tig = lane & 3;
    int wm = (w & 1) * 64, wn = (w >> 1) * 32;

    float acc[4][4][4];
#pragma unroll
    for (int i = 0; i < 4; i++)
#pragma unroll
        for (int j = 0; j < 4; j++)
#pragma unroll
            for (int k = 0; k < 4; k++) acc[i][j][k] = 0.f;

    const int NA = (AHALF && NPASS >= 3) ? 2048 : 1024;
    const int NB = (NPASS >= 2) ? 2048 : 1024;
    for (int kc = 0; kc < K; kc += 64) {
        if (AHALF) {
            for (int idx = t; idx < NA; idx += 256) {
                int arr = idx >> 10, j = idx & 1023, r = j >> 3, c = j & 7;
                const __half* srcp = arr ? Al : Ah;
                uint4 v = make_uint4(0, 0, 0, 0);
                if (m0 + r < M) v = *(const uint4*)(srcp + (size_t)(m0 + r) * K + kc + c * 8);
                *(uint4*)((arr ? sAl : sAh) + r * SMS + c * 8) = v;
            }
        } else {
            for (int idx = t; idx < 1024; idx += 256) {
                int r = idx >> 3, c = idx & 7;
                float4 f0 = make_float4(0.f, 0.f, 0.f, 0.f), f1 = f0;
                if (m0 + r < M) {
                    size_t o = (size_t)(m0 + r) * K + kc + c * 8;
                    if (A0H) {
                        uint4 hv = *(const uint4*)((const __half*)A0 + o);
                        const __half2* hp = (const __half2*)&hv;
                        float2 a01 = __half22float2(hp[0]);
                        float2 a23 = __half22float2(hp[1]);
                        float2 a45 = __half22float2(hp[2]);
                        float2 a67 = __half22float2(hp[3]);
                        f0 = make_float4(a01.x, a01.y, a23.x, a23.y);
                        f1 = make_float4(a45.x, a45.y, a67.x, a67.y);
                    } else {
                        f0 = *(const float4*)(A0 + o);
                        f1 = *(const float4*)(A0 + o + 4);
                    }
                    float4 q0 = *(const float4*)(A1 + o);
                    float4 q1 = *(const float4*)(A1 + o + 4);
                    f0.x += q0.x; f0.y += q0.y; f0.z += q0.z; f0.w += q0.w;
                    f1.x += q1.x; f1.y += q1.y; f1.z += q1.z; f1.w += q1.w;
                }
                __half2 th[2], tl[2];
                split4(f0, th, tl);
                *(__half2*)(sAh + r * SMS + c * 8) = th[0];
                *(__half2*)(sAh + r * SMS + c * 8 + 2) = th[1];
                if (NPASS >= 3) {
                    *(__half2*)(sAl + r * SMS + c * 8) = tl[0];
                    *(__half2*)(sAl + r * SMS + c * 8 + 2) = tl[1];
                }
                split4(f1, th, tl);
                *(__half2*)(sAh + r * SMS + c * 8 + 4) = th[0];
                *(__half2*)(sAh + r * SMS + c * 8 + 6) = th[1];
                if (NPASS >= 3) {
                    *(__half2*)(sAl + r * SMS + c * 8 + 4) = tl[0];
                    *(__half2*)(sAl + r * SMS + c * 8 + 6) = tl[1];
                }
            }
        }
        for (int idx = t; idx < NB; idx += 256) {
            int arr = idx >> 10, j = idx & 1023, r = j >> 3, c = j & 7;
            const __half* srcp = arr ? Bl : Bh;
            uint4 v = *(const uint4*)(srcp + (size_t)(n0 + r) * K + kc + c * 8);
            *(uint4*)((arr ? sBl : sBh) + r * SMS + c * 8) = v;
        }
        __syncthreads();
        compute_chunk<NPASS>(smbase, wm, wn, lane, acc);
        __syncthreads();
    }

    // epilogue (+ optional fused score partials, fused half add)
    float wp[4][2];
    if (SCORE) {
#pragma unroll
        for (int ni = 0; ni < 4; ni++) {
            int col = n0 + wn + ni * 8 + tig * 2;
            wp[ni][0] = Wp[col];
            wp[ni][1] = Wp[col + 1];
        }
    }
    float* sZ = (float*)sm;
#pragma unroll
    for (int mi = 0; mi < 4; mi++) {
#pragma unroll
        for (int half8 = 0; half8 < 2; half8++) {
            int lrow = m0 + wm + mi * 16 + g + half8 * 8;
            float zr = 0.f;
            if (lrow < M) {
                int grow = alist ? alist[lrow] : lrow;
                float rm = degrm ? rsqrtf((float)max(degrm[grow], 1)) : 1.f;
#pragma unroll
                for (int ni = 0; ni < 4; ni++) {
                    int col = n0 + wn + ni * 8 + tig * 2;
                    float v0 = acc[mi][ni][half8 * 2 + 0];
                    float v1 = acc[mi][ni][half8 * 2 + 1];
                    if (bias) { v0 += bias[col]; v1 += bias[col + 1]; }
                    if (act) { v0 = fmaxf(v0, 0.f); v1 = fmaxf(v1, 0.f); }
                    v0 *= rm; v1 *= rm;
                    if (SCORE) zr += v0 * wp[ni][0] + v1 * wp[ni][1];
                    if (ADDH) {
                        uint32_t av = *(const uint32_t*)(addin + (size_t)grow * N + col);
                        float2 af = __half22float2(*(__half2*)&av);
                        v0 += af.x; v1 += af.y;
                    }
                    if (OUTH) {
                        __half2 hv = __floats2half2_rn(v0, v1);
                        *(uint32_t*)((__half*)C + (size_t)grow * N + col) = *(uint32_t*)&hv;
                    } else {
                        *(float2*)(C + (size_t)grow * N + col) = make_float2(v0, v1);
                    }
                }
            }
            if (SCORE) {
                zr += __shfl_xor_sync(0xFFFFFFFFu, zr, 1);
                zr += __shfl_xor_sync(0xFFFFFFFFu, zr, 2);
                if (tig == 0)
                    sZ[(w >> 1) * 128 + wm + mi * 16 + half8 * 8 + g] = zr;
            }
        }
    }
    if (SCORE) {
        __syncthreads();
        if (t < 128 && m0 + t < M) {
            float z = sZ[t] + sZ[128 + t] + sZ[256 + t] + sZ[384 + t];
            int grow = alist ? alist[m0 + t] : m0 + t;
            zpart[grow * 2 + blockIdx.x] = z;
        }
    }
}

// ---------------- pooling ----------------
__global__ void scorekey_kernel(const float* __restrict__ bp, const float* __restrict__ msk) {
    int i = blockIdx.x * blockDim.x + threadIdx.x;
    if (i >= NN) return;
    float z = g_zpart[2 * i] + g_zpart[2 * i + 1] + bp[0];
    float s = 1.f / (1.f + expf(-z));
    g_scores[i] = s;
    float kin = (msk && msk[i] == 0.f) ? -1e9f : s;
    g_keys[i] = f2k(kin);
}

// exact top-K radix select: 3 passes (11+11+10 bits), 2048-bin smem hist,
// parallel chunk-sum selection.
__global__ void topk_kernel(int K, int lvl) {
    __shared__ int hist[2048];
    __shared__ int csum[64];
    __shared__ unsigned s_pref;
    __shared__ int s_kr;
    int tid = threadIdx.x;
    if (tid == 0) { s_pref = 0u; s_kr = K; }
    const int NPAD = ((NN + 1023) / 1024) * 1024;
#pragma unroll
    for (int p = 0; p < 3; p++) {
        const int shift = (p == 0) ? 21 : (p == 1 ? 10 : 0);
        const int nbins = (p == 2) ? 1024 : 2048;
        const int hishift = (p == 1) ? 21 : 10;  // used for p>=1
        hist[tid] = 0;
        if (tid + 1024 < 2048) hist[tid + 1024] = 0;
        __syncthreads();
        unsigned pref = s_pref;
        for (int i = tid; i < NPAD; i += 1024) {
            unsigned bucket = 0xFFFFFFFFu;
            if (i < NN) {
                unsigned k = g_keys[i];
                bool ok = (p == 0) || ((k >> hishift) == (pref >> hishift));
                if (ok) bucket = (k >> shift) & (unsigned)(nbins - 1);
            }
            unsigned peers = __match_any_sync(0xFFFFFFFFu, bucket);
            if (bucket != 0xFFFFFFFFu) {
                int leader = __ffs(peers) - 1;
                if ((tid & 31) == leader) atomicAdd(&hist[bucket], __popc(peers));
            }
        }
        __syncthreads();
        int nch = nbins >> 5;
        if (tid < nch) {
            int s = 0;
#pragma unroll 8
            for (int b = 0; b < 32; b++) s += hist[tid * 32 + b];
            csum[tid] = s;
        }
        __syncthreads();
        if (tid == 0) {
            int kr = s_kr;
            int c = nch - 1;
            for (; c > 0; c--) {
                if (csum[c] >= kr) break;
                kr -= csum[c];
            }
            int b = 31;
            for (; b > 0; b--) {
                int cnt = hist[c * 32 + b];
                if (cnt >= kr) break;
                kr -= cnt;
            }
            s_pref = pref | (((unsigned)(c * 32 + b)) << shift);
            s_kr = kr;
        }
        __syncthreads();
    }
    if (tid == 0) { g_prefix = s_pref; g_nact[lvl] = 0; }
}

__global__ void degm_kernel(const int* __restrict__ src, const int* __restrict__ dst,
                            int* __restrict__ degO, int* __restrict__ degI) {
    int e = blockIdx.x * blockDim.x + threadIdx.x;
    if (e >= NE) return;
    int s = src[e], d = dst[e];
    if (g_keys[s] >= g_prefix && g_keys[d] >= g_prefix) {
        atomicAdd(&degO[s], 1);
        atomicAdd(&degI[d], 1);
    }
}

__global__ void finact_kernel(const int* __restrict__ degO, const int* __restrict__ degI,
                              float* __restrict__ comb, float* __restrict__ dov,
                              float* __restrict__ divv, int* __restrict__ alist, int lvl) {
    int i = blockIdx.x * blockDim.x + threadIdx.x;
    if (i >= NN) return;
    float mo = rsqrtf((float)max(degO[i], 1));
    bool a = g_keys[i] >= g_prefix;
    comb[i] = a ? g_scores[i] * mo : 0.f;
    dov[i] = a ? mo : 0.f;
    divv[i] = rsqrtf((float)max(degI[i], 1));
    if (a) {
        int p = atomicAdd(&g_nact[lvl], 1);
        alist[p] = i;
    }
}

// ---------------- host orchestration ----------------
static inline void* sym(const void* s) {
    void* p = nullptr;
    cudaGetSymbolAddress(&p, (const void*)s);
    return p;
}

extern "C" void kernel_launch(void* const* d_in, const int* in_sizes, int n_in,
                              void* d_out, int out_size) {
    const float* features = (const float*)d_in[0];
    const int* src = (const int*)d_in[1];
    const int* dst = (const int*)d_in[2];
    const float* W_embed = (const float*)d_in[3];
    const float* b_embed = (const float*)d_in[4];
    const float* W_enc0 = (const float*)d_in[5];
    const float* b_enc0 = (const float*)d_in[6];
    const float* W_enc1 = (const float*)d_in[7];
    const float* b_enc1 = (const float*)d_in[8];
    const float* W_p0 = (const float*)d_in[9];
    const float* b_p0 = (const float*)d_in[10];
    const float* W_p1 = (const float*)d_in[11];
    const float* b_p1 = (const float*)d_in[12];
    const float* W_bot = (const float*)d_in[13];
    const float* b_bot = (const float*)d_in[14];
    const float* W_dec0 = (const float*)d_in[15];
    const float* b_dec0 = (const float*)d_in[16];
    const float* W_dec1 = (const float*)d_in[17];
    const float* b_dec1 = (const float*)d_in[18];
    float* out = (float*)d_out;

    __half* p_xah = (__half*)sym(g_xah);
    float* p_h    = (float*)sym(g_h);
    float* p_hid0 = (float*)sym(g_hid0);
    __half* p_h4h = (__half*)sym(g_h4h);
    __half* p_xh  = (__half*)sym(g_xh);
    __half* p_xl  = (__half*)sym(g_xl);
    __half* p_wth = (__half*)sym(g_wth);
    __half* p_wtl = (__half*)sym(g_wtl);
    float* p_zp   = (float*)sym(g_zpart);
    int* p_degout = (int*)sym(g_degout);
    int* p_degO1  = (int*)sym(g_degO1);
    int* p_degI1  = (int*)sym(g_degI1);
    int* p_degO2  = (int*)sym(g_degO2);
    int* p_degI2  = (int*)sym(g_degI2);
    float* p_comb1 = (float*)sym(g_comb1);
    float* p_dov1  = (float*)sym(g_dov1);
    float* p_div1  = (float*)sym(g_div1);
    float* p_comb2 = (float*)sym(g_comb2);
    float* p_dov2  = (float*)sym(g_dov2);
    float* p_div2  = (float*)sym(g_div2);
    int* p_al1 = (int*)sym(g_alist1);
    int* p_al2 = (int*)sym(g_alist2);

    cudaFuncSetAttribute((const void*)gemm_kernel<1, 0, 3, 0, 0, 0>,
                         cudaFuncAttributeMaxDynamicSharedMemorySize, GEMM_SMEM);
    cudaFuncSetAttribute((const void*)gemm_kernel<1, 0, 3, 1, 0, 0>,
                         cudaFuncAttributeMaxDynamicSharedMemorySize, GEMM_SMEM);
    cudaFuncSetAttribute((const void*)gemm_kernel<1, 1, 3, 1, 0, 0>,
                         cudaFuncAttributeMaxDynamicSharedMemorySize, GEMM_SMEM);
    cudaFuncSetAttribute((const void*)gemm_kernel<1, 1, 1, 0, 1, 0>,
                         cudaFuncAttributeMaxDynamicSharedMemorySize, GEMM_SMEM);
    cudaFuncSetAttribute((const void*)gemm_kernel<1, 1, 1, 0, 0, 0>,
                         cudaFuncAttributeMaxDynamicSharedMemorySize, GEMM_SMEM);
    cudaFuncSetAttribute((const void*)gemm_kernel<0, 1, 1, 0, 0, 1>,
                         cudaFuncAttributeMaxDynamicSharedMemorySize, GEMM_SMEM);

    const int TB = 256;
    const int NB_N = (NN + TB - 1) / TB;
    const int NB_E = (NE + TB - 1) / TB;
    dim3 gFull256(2, (NN + 127) / 128);
    dim3 gFull128(1, (NN + 127) / 128);
    dim3 gK1(2, (K1 + 127) / 128);
    dim3 gK2(2, (K2 + 127) / 128);
    auto wgrid = [](int n) { return (n + 7) / 8; };

    // prep + CSR build
    prep_kernel<<<(327680 + TB - 1) / TB, TB>>>(W_embed, W_enc0, W_enc1, W_bot, W_dec0, W_dec1);
    hist_kernel<<<NB_E, TB>>>(src, dst);
    scan1_kernel<<<NSCAN, 1024>>>();
    scan3_kernel<<<NB_N, TB>>>();
    scatter_kernel<<<NB_E, TB>>>(src, dst);

    // L0 (3-pass: feeds top-k path); branch-free agg
    agg_half_kernel<0><<<wgrid(NN), TB>>>(features, nullptr, p_degout, nullptr, nullptr,
                                          p_xh, p_xl, FI, NN);
    gemm_kernel<1, 0, 3, 0, 0, 0><<<gFull256, 256, GEMM_SMEM>>>(
        p_xh, p_xl, nullptr, nullptr, p_wth + WO_EMB, p_wtl + WO_EMB, p_h,
        NN, FI, FH, nullptr, b_embed, nullptr, 1, nullptr, nullptr, nullptr);

    // L1 (3-pass, fused score partials for pool0)
    agg_half_kernel<0><<<wgrid(NN), TB>>>(p_h, nullptr, p_degout, nullptr, nullptr,
                                          p_xh, p_xl, FH, NN);
    gemm_kernel<1, 0, 3, 1, 0, 0><<<gFull256, 256, GEMM_SMEM>>>(
        p_xh, p_xl, nullptr, nullptr, p_wth + WO_ENC0, p_wtl + WO_ENC0, p_hid0,
        NN, FH, FH, nullptr, b_enc0, nullptr, 1, W_p0, p_zp, nullptr);

    // pool0
    scorekey_kernel<<<NB_N, TB>>>(b_p0, nullptr);
    topk_kernel<<<1, 1024>>>(K1, 0);
    degm_kernel<<<NB_E, TB>>>(src, dst, p_degO1, p_degI1);
    finact_kernel<<<NB_N, TB>>>(p_degO1, p_degI1, p_comb1, p_dov1, p_div1, p_al1, 0);

    // L2 (3-pass, fused score partials for pool1) -> fp16 out into xah
    agg_half_kernel<1><<<wgrid(K1), TB>>>(p_hid0, p_comb1, nullptr, p_div1, p_al1,
                                          p_xh, p_xl, FH, K1);
    gemm_kernel<1, 1, 3, 1, 0, 0><<<gK1, 256, GEMM_SMEM>>>(
        p_xh, p_xl, nullptr, nullptr, p_wth + WO_ENC1, p_wtl + WO_ENC1, (float*)p_xah,
        K1, FH, FH, p_al1, b_enc1, nullptr, 1, W_p1, p_zp, nullptr);

    // pool1
    scorekey_kernel<<<NB_N, TB>>>(b_p1, p_dov1);
    topk_kernel<<<1, 1024>>>(K2, 1);
    degm_kernel<<<NB_E, TB>>>(src, dst, p_degO2, p_degI2);
    finact_kernel<<<NB_N, TB>>>(p_degO2, p_degI2, p_comb2, p_dov2, p_div2, p_al2, 1);

    // L3 (single-pass fp16): gather hid1(fp16, in xah) over m2 subgraph; GEMM
    // writes relu(out)+hid1 back into xah at al2 rows (read-before-write, same thread)
    agg_halfin_kernel<<<wgrid(K2), TB>>>(p_xah, p_comb2, p_div2, p_al2, p_xh, K2);
    gemm_kernel<1, 1, 1, 0, 1, 0><<<gK2, 256, GEMM_SMEM>>>(
        p_xh, p_xl, nullptr, nullptr, p_wth + WO_BOT, p_wtl + WO_BOT, (float*)p_xah,
        K2, FH, FH, p_al2, b_bot, nullptr, 1, nullptr, nullptr, p_xah);

    // L4 (single-pass fp16): half gather over xah, GEMM -> h4h (fp16)
    agg_halfin_kernel<<<wgrid(K1), TB>>>(p_xah, p_dov1, p_div1, p_al1, p_xh, K1);
    gemm_kernel<1, 1, 1, 0, 0, 0><<<gK1, 256, GEMM_SMEM>>>(
        p_xh, p_xl, nullptr, nullptr, p_wth + WO_DEC0, p_wtl + WO_DEC0, (float*)p_h4h,
        K1, FH, FH, p_al1, b_dec0, nullptr, 1, nullptr, nullptr, nullptr);

    // L5 (single-pass fp16): fused (h4h(fp16)+hid0(fp32)) split-on-load GEMM -> fp16 out
    gemm_kernel<0, 1, 1, 0, 0, 1><<<gFull128, 256, GEMM_SMEM>>>(
        nullptr, nullptr, (const float*)p_h4h, p_hid0, p_wth + WO_DEC1, p_wtl + WO_DEC1,
        (float*)p_xah, NN, FH, FI, nullptr, nullptr, p_degout, 0,
        nullptr, nullptr, nullptr);
    agg_out_kernel<<<wgrid(NN), TB>>>(p_xah, b_dec1, out);
}